// round 4
// baseline (speedup 1.0000x reference)
#include <cuda_runtime.h>
#include <math.h>
#include <stdint.h>

// ---------------------------------------------------------------------------
// Problem constants
// ---------------------------------------------------------------------------
#define B_SZ    2
#define L_SEQ   2048
#define D_MODEL 1024
#define D_INNER 2048
#define D_STATE 16
#define D_CONV  4
#define DT_RANK 64
#define NROW    (B_SZ * L_SEQ)     // 4096 (b,l) rows
#define E2      (2 * D_INNER)      // 4096
#define XDBL_W  (DT_RANK + 2 * D_STATE)  // 96

// ---------------------------------------------------------------------------
// Scratch (device globals; no cudaMalloc allowed)
// ---------------------------------------------------------------------------
__device__ float g_ht[(size_t)D_MODEL * NROW];                 // h transposed: [d][b*L+l]   16 MB
__device__ float g_xz[(size_t)B_SZ * E2 * L_SEQ];              // [b][e][l]                  64 MB
__device__ float g_uc[(size_t)B_SZ * D_INNER * L_SEQ];         // [b][d][l]                  32 MB
__device__ float g_xdbl[(size_t)NROW * XDBL_W];                // [(b*L+l)][96]              1.5 MB
__device__ float g_delta[(size_t)B_SZ * D_INNER * L_SEQ];      // raw delta (pre-bias)       32 MB
__device__ float g_y[(size_t)B_SZ * D_INNER * L_SEQ];          // scan output                32 MB

// ---------------------------------------------------------------------------
// LayerNorm: one block per (b,l) row of 1024; writes h TRANSPOSED (d-major)
// so the in_proj GEMM reads B coalesced.
// ---------------------------------------------------------------------------
__global__ void ln_kernel(const float* __restrict__ x,
                          const float* __restrict__ gamma,
                          const float* __restrict__ beta) {
    const int row = blockIdx.x;            // 0..4095
    const int tid = threadIdx.x;           // 256 threads
    const float4 v = *(const float4*)(x + (size_t)row * D_MODEL + tid * 4);

    float s  = v.x + v.y + v.z + v.w;
    float sq = v.x * v.x + v.y * v.y + v.z * v.z + v.w * v.w;

    __shared__ float red_s[8], red_q[8];
    // warp reduce
    for (int o = 16; o > 0; o >>= 1) {
        s  += __shfl_xor_sync(0xffffffffu, s, o);
        sq += __shfl_xor_sync(0xffffffffu, sq, o);
    }
    const int wid = tid >> 5, lid = tid & 31;
    if (lid == 0) { red_s[wid] = s; red_q[wid] = sq; }
    __syncthreads();
    if (wid == 0) {
        s  = red_s[lid & 7];
        sq = red_q[lid & 7];
        for (int o = 4; o > 0; o >>= 1) {
            s  += __shfl_xor_sync(0xffffffffu, s, o);
            sq += __shfl_xor_sync(0xffffffffu, sq, o);
        }
        if (lid == 0) { red_s[0] = s; red_q[0] = sq; }
    }
    __syncthreads();
    const float mean = red_s[0] * (1.0f / D_MODEL);
    const float var  = red_q[0] * (1.0f / D_MODEL) - mean * mean;
    const float rstd = rsqrtf(var + 1e-6f);

    const int d0 = tid * 4;
    const float4 g4 = *(const float4*)(gamma + d0);
    const float4 b4 = *(const float4*)(beta + d0);
    g_ht[(size_t)(d0 + 0) * NROW + row] = (v.x - mean) * rstd * g4.x + b4.x;
    g_ht[(size_t)(d0 + 1) * NROW + row] = (v.y - mean) * rstd * g4.y + b4.y;
    g_ht[(size_t)(d0 + 2) * NROW + row] = (v.z - mean) * rstd * g4.z + b4.z;
    g_ht[(size_t)(d0 + 3) * NROW + row] = (v.w - mean) * rstd * g4.w + b4.w;
}

// ---------------------------------------------------------------------------
// Generic tiled SGEMM: C(m,n) = sum_k A(m,k) * B(k,n)
//   A: row-major M x K (lda)
//   B: if !TB: B(k,n) = B[k*ldb + n];  if TB: B(k,n) = B[n*ldb + k]
//   C: if !TC: C[m*ldc + n];           if TC: C[n*ldc + m]  (+ optional residual)
// Batched over blockIdx.z via element strides (A is shared weights).
// BM=BN=128, BK=8, 256 threads, 8x8 register tile.
// ---------------------------------------------------------------------------
template<bool TB, bool TC, bool RES>
__global__ __launch_bounds__(256, 2)
void gemm_kernel(int M, int N, int K,
                 const float* __restrict__ A, int lda,
                 const float* __restrict__ B, int ldb, long bStride,
                 float* __restrict__ C, int ldc, long cStride,
                 const float* __restrict__ R, long rStride) {
    const int bz = blockIdx.z;
    B += (size_t)bz * bStride;
    C += (size_t)bz * cStride;
    if (RES) R += (size_t)bz * rStride;

    const int m0 = blockIdx.y * 128;
    const int n0 = blockIdx.x * 128;
    const int tid = threadIdx.x;

    __shared__ __align__(16) float As[8][128];
    __shared__ __align__(16) float Bs[8][128];

    float acc[8][8];
#pragma unroll
    for (int i = 0; i < 8; i++)
#pragma unroll
        for (int j = 0; j < 8; j++) acc[i][j] = 0.0f;

    const int tr = tid >> 4;   // 0..15
    const int tc = tid & 15;   // 0..15

    for (int k0 = 0; k0 < K; k0 += 8) {
        // --- load A tile (128 x 8) ---
        {
            const int row = tid >> 1;
            const int ks  = (tid & 1) * 4;
            float4 v = make_float4(0.f, 0.f, 0.f, 0.f);
            const int m = m0 + row;
            if (m < M) v = *(const float4*)(A + (size_t)m * lda + k0 + ks);
            As[ks + 0][row] = v.x;
            As[ks + 1][row] = v.y;
            As[ks + 2][row] = v.z;
            As[ks + 3][row] = v.w;
        }
        // --- load B tile (8 x 128) ---
        if (!TB) {
            const int kk = tid >> 5;          // 0..7
            const int nc = (tid & 31) * 4;    // 0..124
            float4 v = make_float4(0.f, 0.f, 0.f, 0.f);
            if (n0 + nc < N) v = *(const float4*)(B + (size_t)(k0 + kk) * ldb + n0 + nc);
            *(float4*)(&Bs[kk][nc]) = v;
        } else {
            const int nr = tid >> 1;
            const int ks = (tid & 1) * 4;
            float4 v = make_float4(0.f, 0.f, 0.f, 0.f);
            if (n0 + nr < N) v = *(const float4*)(B + (size_t)(n0 + nr) * ldb + k0 + ks);
            Bs[ks + 0][nr] = v.x;
            Bs[ks + 1][nr] = v.y;
            Bs[ks + 2][nr] = v.z;
            Bs[ks + 3][nr] = v.w;
        }
        __syncthreads();

#pragma unroll
        for (int kk = 0; kk < 8; kk++) {
            float4 a0 = *(const float4*)(&As[kk][tr * 8]);
            float4 a1 = *(const float4*)(&As[kk][tr * 8 + 4]);
            float4 b0 = *(const float4*)(&Bs[kk][tc * 8]);
            float4 b1 = *(const float4*)(&Bs[kk][tc * 8 + 4]);
            float av[8] = {a0.x, a0.y, a0.z, a0.w, a1.x, a1.y, a1.z, a1.w};
            float bv[8] = {b0.x, b0.y, b0.z, b0.w, b1.x, b1.y, b1.z, b1.w};
#pragma unroll
            for (int i = 0; i < 8; i++)
#pragma unroll
                for (int j = 0; j < 8; j++) acc[i][j] = fmaf(av[i], bv[j], acc[i][j]);
        }
        __syncthreads();
    }

    // --- store ---
#pragma unroll
    for (int i = 0; i < 8; i++) {
        const int m = m0 + tr * 8 + i;
        if (m >= M) continue;
#pragma unroll
        for (int j = 0; j < 8; j++) {
            const int n = n0 + tc * 8 + j;
            if (n >= N) continue;
            if (TC) {
                float v = acc[i][j];
                if (RES) v += R[(size_t)n * ldc + m];
                C[(size_t)n * ldc + m] = v;
            } else {
                C[(size_t)m * ldc + n] = acc[i][j];
            }
        }
    }
}

// ---------------------------------------------------------------------------
// Depthwise causal conv (k=4) + bias + SiLU.  u = g_xz[:, 0:2048, :]
// ---------------------------------------------------------------------------
__global__ void conv_kernel(const float* __restrict__ conv_w,
                            const float* __restrict__ conv_b) {
    const int l = blockIdx.x * 256 + threadIdx.x;
    const int d = blockIdx.y;
    const int b = blockIdx.z;
    const float* u = g_xz + ((size_t)b * E2 + d) * L_SEQ;
    const float w0 = conv_w[d * 4 + 0];
    const float w1 = conv_w[d * 4 + 1];
    const float w2 = conv_w[d * 4 + 2];
    const float w3 = conv_w[d * 4 + 3];
    float s = conv_b[d];
    s += w3 * u[l];
    if (l >= 1) s += w2 * u[l - 1];
    if (l >= 2) s += w1 * u[l - 2];
    if (l >= 3) s += w0 * u[l - 3];
    const float sil = s / (1.0f + expf(-s));
    g_uc[((size_t)b * D_INNER + d) * L_SEQ + l] = sil;
}

// ---------------------------------------------------------------------------
// Selective scan. Half-warp (16 lanes = 16 states) per channel d.
// 256 threads/block = 16 channels/block. grid = (D_INNER/16, B).
// y[b,d,l] = (sum_n state_n * C_n + uc*D) * silu(z)
// ---------------------------------------------------------------------------
__global__ __launch_bounds__(256)
void scan_kernel(const float* __restrict__ A_log,
                 const float* __restrict__ Dvec,
                 const float* __restrict__ dt_b) {
    const int tid  = threadIdx.x;
    const int lane = tid & 31;
    const int n    = lane & 15;           // state index
    const int half = lane >> 4;           // 0/1 within warp
    const int w    = tid >> 5;            // warp 0..7
    const int d    = blockIdx.x * 16 + w * 2 + half;
    const int b    = blockIdx.y;

    const float An  = -expf(A_log[d * D_STATE + n]);
    const float Dd  = Dvec[d];
    const float dtb = dt_b[d];

    const float* dp = g_delta + ((size_t)b * D_INNER + d) * L_SEQ;
    const float* up = g_uc    + ((size_t)b * D_INNER + d) * L_SEQ;
    const float* zp = g_xz    + ((size_t)b * E2 + D_INNER + d) * L_SEQ;
    const float* xd = g_xdbl  + (size_t)b * L_SEQ * XDBL_W;
    float*       yp = g_y     + ((size_t)b * D_INNER + d) * L_SEQ;

    float state = 0.0f;
    float ybuf[4];

    for (int l = 0; l < L_SEQ; l++) {
        const float draw = __ldg(dp + l);
        const float u    = __ldg(up + l);
        const float zz   = __ldg(zp + l);
        const float Bn   = __ldg(xd + (size_t)l * XDBL_W + DT_RANK + n);
        const float Cn   = __ldg(xd + (size_t)l * XDBL_W + DT_RANK + D_STATE + n);

        float dv = draw + dtb;
        dv = (dv > 20.0f) ? dv : log1pf(expf(dv));       // softplus
        const float dA = expf(dv * An);
        state = fmaf(dA, state, dv * Bn * u);

        float yc = state * Cn;
        yc += __shfl_xor_sync(0xffffffffu, yc, 1);
        yc += __shfl_xor_sync(0xffffffffu, yc, 2);
        yc += __shfl_xor_sync(0xffffffffu, yc, 4);
        yc += __shfl_xor_sync(0xffffffffu, yc, 8);

        if (n == 0) {
            const float sil = zz / (1.0f + expf(-zz));
            ybuf[l & 3] = (yc + u * Dd) * sil;
            if ((l & 3) == 3) {
                *(float4*)(yp + l - 3) = make_float4(ybuf[0], ybuf[1], ybuf[2], ybuf[3]);
            }
        }
    }
}

// ---------------------------------------------------------------------------
// Launch
// ---------------------------------------------------------------------------
extern "C" void kernel_launch(void* const* d_in, const int* in_sizes, int n_in,
                              void* d_out, int out_size) {
    const float* x        = (const float*)d_in[0];
    const float* ln_gamma = (const float*)d_in[1];
    const float* ln_beta  = (const float*)d_in[2];
    const float* in_proj  = (const float*)d_in[3];
    const float* conv_w   = (const float*)d_in[4];
    const float* conv_b   = (const float*)d_in[5];
    const float* x_proj   = (const float*)d_in[6];
    const float* dt_proj  = (const float*)d_in[7];
    const float* dt_pb    = (const float*)d_in[8];
    const float* A_log    = (const float*)d_in[9];
    const float* Dvec     = (const float*)d_in[10];
    const float* out_proj = (const float*)d_in[11];
    float* out = (float*)d_out;

    float *ht, *xz, *uc, *xdbl, *delta, *yb;
    cudaGetSymbolAddress((void**)&ht,    g_ht);
    cudaGetSymbolAddress((void**)&xz,    g_xz);
    cudaGetSymbolAddress((void**)&uc,    g_uc);
    cudaGetSymbolAddress((void**)&xdbl,  g_xdbl);
    cudaGetSymbolAddress((void**)&delta, g_delta);
    cudaGetSymbolAddress((void**)&yb,    g_y);

    // 1. LayerNorm -> h^T
    ln_kernel<<<NROW, 256>>>(x, ln_gamma, ln_beta);

    // 2. in_proj: xz[b,e,l] = in_proj[e,:] . h[b,l,:]
    //    M=4096, N=2048, K=1024; B(k,n) = ht[k*4096 + b*2048 + n]
    gemm_kernel<false, false, false><<<dim3(16, 32, B_SZ), 256>>>(
        E2, L_SEQ, D_MODEL,
        in_proj, D_MODEL,
        ht, NROW, (long)L_SEQ,
        xz, L_SEQ, (long)E2 * L_SEQ,
        nullptr, 0);

    // 3. conv + SiLU -> uc
    conv_kernel<<<dim3(L_SEQ / 256, D_INNER, B_SZ), 256>>>(conv_w, conv_b);

    // 4. x_proj: x_dbl[(b,l),e] = x_proj[e,:] . uc[b,:,l]  (TC: C[n*96+m])
    gemm_kernel<false, true, false><<<dim3(16, 1, B_SZ), 256>>>(
        XDBL_W, L_SEQ, D_INNER,
        x_proj, D_INNER,
        uc, L_SEQ, (long)D_INNER * L_SEQ,
        xdbl, XDBL_W, (long)L_SEQ * XDBL_W,
        nullptr, 0);

    // 5. dt_proj: delta[b,d,l] = dt_proj[d,:] . dt[b,l,:]  (TB: B(k,n)=xdbl[n*96+k])
    gemm_kernel<true, false, false><<<dim3(16, 16, B_SZ), 256>>>(
        D_INNER, L_SEQ, DT_RANK,
        dt_proj, DT_RANK,
        xdbl, XDBL_W, (long)L_SEQ * XDBL_W,
        delta, L_SEQ, (long)D_INNER * L_SEQ,
        nullptr, 0);

    // 6. selective scan -> y
    scan_kernel<<<dim3(D_INNER / 16, B_SZ), 256>>>(A_log, Dvec, dt_pb);

    // 7. out_proj + residual: out[b,l,e] = out_proj[e,:] . y[b,:,l] + x[b,l,e]
    gemm_kernel<false, true, true><<<dim3(16, 8, B_SZ), 256>>>(
        D_MODEL, L_SEQ, D_INNER,
        out_proj, D_INNER,
        yb, L_SEQ, (long)D_INNER * L_SEQ,
        out, D_MODEL, (long)L_SEQ * D_MODEL,
        x, (long)L_SEQ * D_MODEL);
}

// round 10
// speedup vs baseline: 3.0085x; 3.0085x over previous
#include <cuda_runtime.h>
#include <math.h>
#include <stdint.h>

// ---------------------------------------------------------------------------
// Problem constants
// ---------------------------------------------------------------------------
#define B_SZ    2
#define L_SEQ   2048
#define D_MODEL 1024
#define D_INNER 2048
#define D_STATE 16
#define D_CONV  4
#define DT_RANK 64
#define NROW    (B_SZ * L_SEQ)           // 4096 rows n=(b,l)
#define E2      (2 * D_INNER)            // 4096
#define XDBL_W  (DT_RANK + 2 * D_STATE)  // 96

// ---------------------------------------------------------------------------
// Scratch (device globals; no cudaMalloc allowed)
// ---------------------------------------------------------------------------
__device__ float g_h[(size_t)NROW * D_MODEL];           // LN out [n][d]
__device__ float g_xzT[(size_t)NROW * E2];              // in_proj out [n][e]
__device__ float g_uct[(size_t)NROW * D_INNER];         // conv out [n][d]
__device__ float g_ucl[(size_t)B_SZ * D_INNER * L_SEQ]; // conv out [b][d][l]
__device__ float g_xdbl[(size_t)NROW * XDBL_W];         // x_proj out [n][96]
__device__ float g_delta[(size_t)D_INNER * NROW];       // softplus(dt) [d][n]
__device__ float g_yt[(size_t)NROW * D_INNER];          // scan out [n][d]

// ---------------------------------------------------------------------------
// tf32 helpers
// ---------------------------------------------------------------------------
__device__ __forceinline__ uint32_t to_tf32(float f) {
    uint32_t u;
    asm("cvt.rna.tf32.f32 %0, %1;" : "=r"(u) : "f"(f));
    return u;
}
__device__ __forceinline__ void mma_tf32(float* d, const uint32_t* a, const uint32_t* b) {
    asm volatile(
        "mma.sync.aligned.m16n8k8.row.col.f32.tf32.tf32.f32 "
        "{%0,%1,%2,%3}, {%4,%5,%6,%7}, {%8,%9}, {%0,%1,%2,%3};\n"
        : "+f"(d[0]), "+f"(d[1]), "+f"(d[2]), "+f"(d[3])
        : "r"(a[0]), "r"(a[1]), "r"(a[2]), "r"(a[3]), "r"(b[0]), "r"(b[1]));
}

// ---------------------------------------------------------------------------
// tf32 mma.sync GEMM:
//   Ct[n][m] (ldc) = sum_k Act[n][k] * W[m][k]   (+ optional R[n][m])
// mma-M = activation rows (tile 128), mma-N = features (tile 128), chunk K=32.
// 256 threads = 2(M) x 4(N) warps, each warp 64x32 = 4x4 m16n8k8 tiles.
// Double-buffered smem, stride-36 rows (conflict-free fragment LDS).
// ---------------------------------------------------------------------------
#define ROW_STR 36
#define BUF_U32 (128 * ROW_STR)          // 4608 words = 18432 B per buffer
#define GSMEM_BYTES (4 * BUF_U32 * 4)    // A0 A1 B0 B1 = 73728 B

template<bool RES>
__global__ __launch_bounds__(256)
void gemm_mma(const float* __restrict__ W, int K, int Mvalid,
              const float* __restrict__ Act,
              float* __restrict__ Ct, int ldc,
              const float* __restrict__ R) {
    extern __shared__ __align__(16) uint32_t smem[];
    const int tid    = threadIdx.x;
    const int lane   = tid & 31;
    const int wid    = tid >> 5;
    const int qid    = lane >> 2;    // 0..7
    const int qtid   = lane & 3;     // 0..3
    const int warp_m = wid & 1;      // 2 warps along activation rows
    const int warp_n = wid >> 1;     // 4 warps along features
    const int n0     = blockIdx.x * 128;   // activation-row block
    const int m0     = blockIdx.y * 128;   // feature block

    float acc[4][4][4];
#pragma unroll
    for (int mt = 0; mt < 4; mt++)
#pragma unroll
        for (int nt = 0; nt < 4; nt++)
#pragma unroll
            for (int q = 0; q < 4; q++) acc[mt][nt][q] = 0.0f;

    const int KI = K >> 5;
    float4 pa[4], pb[4];

    // --- prologue: stage chunk 0 ---
#pragma unroll
    for (int jj = 0; jj < 4; jj++) {
        const int f   = jj * 256 + tid;
        const int row = f >> 3;
        const int kq  = (f & 7) * 4;
        pa[jj] = *(const float4*)(Act + (size_t)(n0 + row) * K + kq);
        pb[jj] = (m0 + row < Mvalid)
               ? *(const float4*)(W + (size_t)(m0 + row) * K + kq)
               : make_float4(0.f, 0.f, 0.f, 0.f);
    }
    {
        uint32_t* sA = smem;
        uint32_t* sB = smem + 2 * BUF_U32;
#pragma unroll
        for (int jj = 0; jj < 4; jj++) {
            const int f   = jj * 256 + tid;
            const int row = f >> 3;
            const int kq  = (f & 7) * 4;
            uint4 ua = make_uint4(to_tf32(pa[jj].x), to_tf32(pa[jj].y),
                                  to_tf32(pa[jj].z), to_tf32(pa[jj].w));
            uint4 ub = make_uint4(to_tf32(pb[jj].x), to_tf32(pb[jj].y),
                                  to_tf32(pb[jj].z), to_tf32(pb[jj].w));
            *(uint4*)(sA + row * ROW_STR + kq) = ua;
            *(uint4*)(sB + row * ROW_STR + kq) = ub;
        }
    }
    __syncthreads();

    for (int i = 0; i < KI; i++) {
        const int p = i & 1;
        // prefetch next chunk into registers
        if (i + 1 < KI) {
            const int k0 = (i + 1) << 5;
#pragma unroll
            for (int jj = 0; jj < 4; jj++) {
                const int f   = jj * 256 + tid;
                const int row = f >> 3;
                const int kq  = (f & 7) * 4;
                pa[jj] = *(const float4*)(Act + (size_t)(n0 + row) * K + k0 + kq);
                pb[jj] = (m0 + row < Mvalid)
                       ? *(const float4*)(W + (size_t)(m0 + row) * K + k0 + kq)
                       : make_float4(0.f, 0.f, 0.f, 0.f);
            }
        }

        // compute from buffer p
        {
            const uint32_t* sA = smem + p * BUF_U32;
            const uint32_t* sB = smem + (2 + p) * BUF_U32;
#pragma unroll
            for (int ks = 0; ks < 4; ks++) {
                const int kb = ks * 8;
                uint32_t af[4][4], bf[4][2];
#pragma unroll
                for (int mt = 0; mt < 4; mt++) {
                    const int r = warp_m * 64 + mt * 16 + qid;
                    af[mt][0] = sA[(size_t)r * ROW_STR + kb + qtid];
                    af[mt][1] = sA[(size_t)(r + 8) * ROW_STR + kb + qtid];
                    af[mt][2] = sA[(size_t)r * ROW_STR + kb + qtid + 4];
                    af[mt][3] = sA[(size_t)(r + 8) * ROW_STR + kb + qtid + 4];
                }
#pragma unroll
                for (int nt = 0; nt < 4; nt++) {
                    const int fr = warp_n * 32 + nt * 8 + qid;
                    bf[nt][0] = sB[(size_t)fr * ROW_STR + kb + qtid];
                    bf[nt][1] = sB[(size_t)fr * ROW_STR + kb + qtid + 4];
                }
#pragma unroll
                for (int mt = 0; mt < 4; mt++)
#pragma unroll
                    for (int nt = 0; nt < 4; nt++)
                        mma_tf32(acc[mt][nt], af[mt], bf[nt]);
            }
        }

        // stage next chunk into other buffer
        if (i + 1 < KI) {
            uint32_t* sA = smem + (1 - p) * BUF_U32;
            uint32_t* sB = smem + (2 + (1 - p)) * BUF_U32;
#pragma unroll
            for (int jj = 0; jj < 4; jj++) {
                const int f   = jj * 256 + tid;
                const int row = f >> 3;
                const int kq  = (f & 7) * 4;
                uint4 ua = make_uint4(to_tf32(pa[jj].x), to_tf32(pa[jj].y),
                                      to_tf32(pa[jj].z), to_tf32(pa[jj].w));
                uint4 ub = make_uint4(to_tf32(pb[jj].x), to_tf32(pb[jj].y),
                                      to_tf32(pb[jj].z), to_tf32(pb[jj].w));
                *(uint4*)(sA + row * ROW_STR + kq) = ua;
                *(uint4*)(sB + row * ROW_STR + kq) = ub;
            }
            __syncthreads();
        }
    }

    // --- epilogue: direct coalesced float2 stores of Ct[n][m] ---
#pragma unroll
    for (int mt = 0; mt < 4; mt++) {
        const int n = n0 + warp_m * 64 + mt * 16 + qid;
#pragma unroll
        for (int nt = 0; nt < 4; nt++) {
            const int m = m0 + warp_n * 32 + nt * 8 + 2 * qtid;
            if (m < Mvalid) {
                float2 v0 = make_float2(acc[mt][nt][0], acc[mt][nt][1]);
                float2 v1 = make_float2(acc[mt][nt][2], acc[mt][nt][3]);
                if (RES) {
                    const float2 r0 = *(const float2*)(R + (size_t)n * ldc + m);
                    const float2 r1 = *(const float2*)(R + (size_t)(n + 8) * ldc + m);
                    v0.x += r0.x; v0.y += r0.y;
                    v1.x += r1.x; v1.y += r1.y;
                }
                *(float2*)(Ct + (size_t)n * ldc + m) = v0;
                *(float2*)(Ct + (size_t)(n + 8) * ldc + m) = v1;
            }
        }
    }
}

// ---------------------------------------------------------------------------
// LayerNorm: one block per row n; writes h[n][d] row-major.
// ---------------------------------------------------------------------------
__global__ void ln_kernel(const float* __restrict__ x,
                          const float* __restrict__ gamma,
                          const float* __restrict__ beta) {
    const int row = blockIdx.x;
    const int tid = threadIdx.x;           // 256
    const float4 v = *(const float4*)(x + (size_t)row * D_MODEL + tid * 4);

    float s  = v.x + v.y + v.z + v.w;
    float sq = v.x * v.x + v.y * v.y + v.z * v.z + v.w * v.w;

    __shared__ float red_s[8], red_q[8];
    for (int o = 16; o > 0; o >>= 1) {
        s  += __shfl_xor_sync(0xffffffffu, s, o);
        sq += __shfl_xor_sync(0xffffffffu, sq, o);
    }
    const int wid = tid >> 5, lid = tid & 31;
    if (lid == 0) { red_s[wid] = s; red_q[wid] = sq; }
    __syncthreads();
    if (wid == 0) {
        s  = red_s[lid & 7];
        sq = red_q[lid & 7];
        for (int o = 4; o > 0; o >>= 1) {
            s  += __shfl_xor_sync(0xffffffffu, s, o);
            sq += __shfl_xor_sync(0xffffffffu, sq, o);
        }
        if (lid == 0) { red_s[0] = s; red_q[0] = sq; }
    }
    __syncthreads();
    const float mean = red_s[0] * (1.0f / D_MODEL);
    const float var  = red_q[0] * (1.0f / D_MODEL) - mean * mean;
    const float rstd = rsqrtf(var + 1e-6f);

    const int d0 = tid * 4;
    const float4 g4 = *(const float4*)(gamma + d0);
    const float4 b4 = *(const float4*)(beta + d0);
    float4 o4;
    o4.x = (v.x - mean) * rstd * g4.x + b4.x;
    o4.y = (v.y - mean) * rstd * g4.y + b4.y;
    o4.z = (v.z - mean) * rstd * g4.z + b4.z;
    o4.w = (v.w - mean) * rstd * g4.w + b4.w;
    *(float4*)(g_h + (size_t)row * D_MODEL + d0) = o4;
}

// ---------------------------------------------------------------------------
// Depthwise causal conv(k=4)+bias+SiLU. Reads xzT[n][e<2048]; writes BOTH
// uct[n][d] (coalesced) and ucl[b][d][l] (smem transpose).
// Tile: 32 d x 64 l per block. 256 threads.
// ---------------------------------------------------------------------------
__global__ __launch_bounds__(256)
void conv_kernel(const float* __restrict__ conv_w,
                 const float* __restrict__ conv_b) {
    __shared__ float s_in[67][33];
    __shared__ float s_out[64][33];
    const int tid = threadIdx.x;
    const int d0  = blockIdx.x * 32;
    const int l0  = blockIdx.y * 64;
    const int b   = blockIdx.z;

    for (int base = tid; base < 67 * 32; base += 256) {
        const int r = base >> 5;
        const int c = base & 31;
        const int l = l0 - 3 + r;
        float v = 0.0f;
        if (l >= 0) v = g_xzT[((size_t)b * L_SEQ + l) * E2 + d0 + c];
        s_in[r][c] = v;
    }
    __syncthreads();

    for (int base = tid; base < 64 * 32; base += 256) {
        const int ll = base >> 5;
        const int c  = base & 31;
        const int d  = d0 + c;
        const float4 w = *(const float4*)(conv_w + d * 4);
        float s = conv_b[d];
        s = fmaf(w.x, s_in[ll + 0][c], s);
        s = fmaf(w.y, s_in[ll + 1][c], s);
        s = fmaf(w.z, s_in[ll + 2][c], s);
        s = fmaf(w.w, s_in[ll + 3][c], s);
        const float v = s / (1.0f + expf(-s));
        s_out[ll][c] = v;
        g_uct[((size_t)b * L_SEQ + l0 + ll) * D_INNER + d] = v;
    }
    __syncthreads();

    // transpose store: coalesced along l
    const int ll = tid & 63;
    const int cg = tid >> 6;   // 0..3
#pragma unroll
    for (int j = 0; j < 8; j++) {
        const int c = cg * 8 + j;
        g_ucl[((size_t)b * D_INNER + d0 + c) * L_SEQ + l0 + ll] = s_out[ll][c];
    }
}

// ---------------------------------------------------------------------------
// FFMA GEMM (dt_proj only): C(m,n) = sum_k A(m,k)*B(n,k), K=64,
// epilogue: bias[m] + softplus; stores delta[m][n] (ldc = NROW).
// ---------------------------------------------------------------------------
__global__ __launch_bounds__(256, 2)
void gemm_dt(int M, int N, int K,
             const float* __restrict__ A, int lda,
             const float* __restrict__ B, int ldb,
             float* __restrict__ C, int ldc,
             const float* __restrict__ bias) {
    const int m0 = blockIdx.y * 128;
    const int n0 = blockIdx.x * 128;
    const int tid = threadIdx.x;

    __shared__ __align__(16) float As[8][128];
    __shared__ __align__(16) float Bs[8][128];

    float acc[8][8];
#pragma unroll
    for (int i = 0; i < 8; i++)
#pragma unroll
        for (int j = 0; j < 8; j++) acc[i][j] = 0.0f;

    const int tr = tid >> 4;
    const int tc = tid & 15;

    for (int k0 = 0; k0 < K; k0 += 8) {
        {
            const int row = tid >> 1;
            const int ks  = (tid & 1) * 4;
            float4 v = *(const float4*)(A + (size_t)(m0 + row) * lda + k0 + ks);
            As[ks + 0][row] = v.x; As[ks + 1][row] = v.y;
            As[ks + 2][row] = v.z; As[ks + 3][row] = v.w;
        }
        {
            const int nr = tid >> 1;
            const int ks = (tid & 1) * 4;
            float4 v = *(const float4*)(B + (size_t)(n0 + nr) * ldb + k0 + ks);
            Bs[ks + 0][nr] = v.x; Bs[ks + 1][nr] = v.y;
            Bs[ks + 2][nr] = v.z; Bs[ks + 3][nr] = v.w;
        }
        __syncthreads();
#pragma unroll
        for (int kk = 0; kk < 8; kk++) {
            float4 a0 = *(const float4*)(&As[kk][tr * 8]);
            float4 a1 = *(const float4*)(&As[kk][tr * 8 + 4]);
            float4 b0 = *(const float4*)(&Bs[kk][tc * 8]);
            float4 b1 = *(const float4*)(&Bs[kk][tc * 8 + 4]);
            float av[8] = {a0.x, a0.y, a0.z, a0.w, a1.x, a1.y, a1.z, a1.w};
            float bv[8] = {b0.x, b0.y, b0.z, b0.w, b1.x, b1.y, b1.z, b1.w};
#pragma unroll
            for (int i = 0; i < 8; i++)
#pragma unroll
                for (int j = 0; j < 8; j++) acc[i][j] = fmaf(av[i], bv[j], acc[i][j]);
        }
        __syncthreads();
    }

#pragma unroll
    for (int i = 0; i < 8; i++) {
        const int m = m0 + tr * 8 + i;
        const float bm = bias[m];
#pragma unroll
        for (int j = 0; j < 8; j++) {
            const int n = n0 + tc * 8 + j;
            float v = acc[i][j] + bm;
            v = (v > 20.0f) ? v : log1pf(expf(v));
            C[(size_t)m * ldc + n] = v;
        }
    }
}

// ---------------------------------------------------------------------------
// Selective scan. Half-warp (16 lanes = 16 states) per channel d.
// delta already softplus'd; silu(z) applied later. Writes yt[n][d].
// ---------------------------------------------------------------------------
__global__ __launch_bounds__(256)
void scan_kernel(const float* __restrict__ A_log,
                 const float* __restrict__ Dvec) {
    const int tid  = threadIdx.x;
    const int lane = tid & 31;
    const int n    = lane & 15;
    const int half = lane >> 4;
    const int w    = tid >> 5;
    const int d    = blockIdx.x * 16 + w * 2 + half;
    const int b    = blockIdx.y;

    const float An = -expf(A_log[d * D_STATE + n]);
    const float Dd = Dvec[d];

    const float* dp = g_delta + (size_t)d * NROW + b * L_SEQ;
    const float* up = g_ucl   + ((size_t)b * D_INNER + d) * L_SEQ;
    const float* xd = g_xdbl  + (size_t)b * L_SEQ * XDBL_W;
    float*       yp = g_yt    + (size_t)b * L_SEQ * D_INNER + d;

    float state = 0.0f;

#pragma unroll 4
    for (int l = 0; l < L_SEQ; l++) {
        const float dv = __ldg(dp + l);
        const float u  = __ldg(up + l);
        const float Bn = __ldg(xd + (size_t)l * XDBL_W + DT_RANK + n);
        const float Cn = __ldg(xd + (size_t)l * XDBL_W + DT_RANK + D_STATE + n);

        const float dA = __expf(dv * An);
        state = fmaf(dA, state, dv * Bn * u);

        float yc = state * Cn;
        yc += __shfl_xor_sync(0xffffffffu, yc, 1);
        yc += __shfl_xor_sync(0xffffffffu, yc, 2);
        yc += __shfl_xor_sync(0xffffffffu, yc, 4);
        yc += __shfl_xor_sync(0xffffffffu, yc, 8);

        if (n == 0) {
            yp[(size_t)l * D_INNER] = yc + u * Dd;
        }
    }
}

// ---------------------------------------------------------------------------
// y *= silu(z) elementwise (coalesced). yt[n][d], z = xzT[n][2048+d].
// ---------------------------------------------------------------------------
__global__ void ymult_kernel() {
    const size_t i = (size_t)blockIdx.x * 256 + threadIdx.x;   // float4 index
    const int nrow = (int)(i >> 9);            // 512 float4 per row of 2048
    const int d4   = ((int)i & 511) * 4;
    const float4 z4 = *(const float4*)(g_xzT + (size_t)nrow * E2 + D_INNER + d4);
    float4 y4 = *(float4*)(g_yt + (size_t)nrow * D_INNER + d4);
    y4.x *= z4.x / (1.0f + expf(-z4.x));
    y4.y *= z4.y / (1.0f + expf(-z4.y));
    y4.z *= z4.z / (1.0f + expf(-z4.z));
    y4.w *= z4.w / (1.0f + expf(-z4.w));
    *(float4*)(g_yt + (size_t)nrow * D_INNER + d4) = y4;
}

// ---------------------------------------------------------------------------
// Launch
// ---------------------------------------------------------------------------
extern "C" void kernel_launch(void* const* d_in, const int* in_sizes, int n_in,
                              void* d_out, int out_size) {
    const float* x        = (const float*)d_in[0];
    const float* ln_gamma = (const float*)d_in[1];
    const float* ln_beta  = (const float*)d_in[2];
    const float* in_proj  = (const float*)d_in[3];
    const float* conv_w   = (const float*)d_in[4];
    const float* conv_b   = (const float*)d_in[5];
    const float* x_proj   = (const float*)d_in[6];
    const float* dt_proj  = (const float*)d_in[7];
    const float* dt_pb    = (const float*)d_in[8];
    const float* A_log    = (const float*)d_in[9];
    const float* Dvec     = (const float*)d_in[10];
    const float* out_proj = (const float*)d_in[11];
    float* out = (float*)d_out;

    float *h, *uct, *xdbl, *delta, *yt, *xzT;
    cudaGetSymbolAddress((void**)&h,     g_h);
    cudaGetSymbolAddress((void**)&xzT,   g_xzT);
    cudaGetSymbolAddress((void**)&uct,   g_uct);
    cudaGetSymbolAddress((void**)&xdbl,  g_xdbl);
    cudaGetSymbolAddress((void**)&delta, g_delta);
    cudaGetSymbolAddress((void**)&yt,    g_yt);

    static bool attr_set = false;
    if (!attr_set) {
        cudaFuncSetAttribute(gemm_mma<false>, cudaFuncAttributeMaxDynamicSharedMemorySize, GSMEM_BYTES);
        cudaFuncSetAttribute(gemm_mma<true>,  cudaFuncAttributeMaxDynamicSharedMemorySize, GSMEM_BYTES);
        attr_set = true;
    }

    // 1. LayerNorm -> h[n][d]
    ln_kernel<<<NROW, 256>>>(x, ln_gamma, ln_beta);

    // 2. in_proj (mma tf32): xzT[n][e] = h[n][:] . W_in[e][:]
    gemm_mma<false><<<dim3(NROW / 128, E2 / 128), 256, GSMEM_BYTES>>>(
        in_proj, D_MODEL, E2, h, xzT, E2, nullptr);

    // 3. conv + SiLU -> uct[n][d], ucl[b][d][l]
    conv_kernel<<<dim3(D_INNER / 32, L_SEQ / 64, B_SZ), 256>>>(conv_w, conv_b);

    // 4. x_proj (mma tf32): xdbl[n][0:96] = uct[n][:] . xW[e][:]  (M=96 pad 128)
    gemm_mma<false><<<dim3(NROW / 128, 1), 256, GSMEM_BYTES>>>(
        x_proj, D_INNER, XDBL_W, uct, xdbl, XDBL_W, nullptr);

    // 5. dt_proj (FFMA) + bias + softplus -> delta[d][n]
    gemm_dt<<<dim3(NROW / 128, D_INNER / 128), 256>>>(
        D_INNER, NROW, DT_RANK,
        dt_proj, DT_RANK, xdbl, XDBL_W, delta, NROW, dt_pb);

    // 6. selective scan -> yt[n][d]
    scan_kernel<<<dim3(D_INNER / 16, B_SZ), 256>>>(A_log, Dvec);

    // 7. y *= silu(z)
    ymult_kernel<<<(NROW * D_INNER / 4) / 256, 256>>>();

    // 8. out_proj (mma tf32) + residual: out[n][e] = yt[n][:] . oW[e][:] + x
    gemm_mma<true><<<dim3(NROW / 128, D_MODEL / 128), 256, GSMEM_BYTES>>>(
        out_proj, D_INNER, D_MODEL, yt, out, D_MODEL, x);
}

// round 11
// speedup vs baseline: 3.4611x; 1.1505x over previous
#include <cuda_runtime.h>
#include <math.h>
#include <stdint.h>

// ---------------------------------------------------------------------------
// Problem constants
// ---------------------------------------------------------------------------
#define B_SZ    2
#define L_SEQ   2048
#define D_MODEL 1024
#define D_INNER 2048
#define D_STATE 16
#define D_CONV  4
#define DT_RANK 64
#define NROW    (B_SZ * L_SEQ)           // 4096 rows n=(b,l)
#define E2      (2 * D_INNER)            // 4096
#define XDBL_W  (DT_RANK + 2 * D_STATE)  // 96
#define XSPLIT  4                        // split-K slices for x_proj

// ---------------------------------------------------------------------------
// Scratch (device globals; no cudaMalloc allowed)
// ---------------------------------------------------------------------------
__device__ float g_h[(size_t)NROW * D_MODEL];            // LN out [n][d] (tf32-rounded)
__device__ float g_xzT[(size_t)NROW * E2];               // in_proj out [n][e]
__device__ float g_uct[(size_t)NROW * D_INNER];          // conv out [n][d] (tf32-rounded)
__device__ float g_ucl[(size_t)B_SZ * D_INNER * L_SEQ];  // conv out [b][d][l] (full fp32)
__device__ float g_xdbl[(size_t)NROW * XDBL_W];          // x_proj out [n][96] (tf32-rounded)
__device__ float g_deltaT[(size_t)NROW * D_INNER];       // softplus(dt) [n][d]
__device__ float g_yt[(size_t)NROW * D_INNER];           // scan out [n][d] (tf32-rounded)
// tf32-rounded weights (converted every launch)
__device__ float g_win[(size_t)E2 * D_MODEL];            // 4096x1024
__device__ float g_wx[(size_t)128 * D_INNER];            // 96x2048 padded to 128 rows
__device__ float g_wdt[(size_t)D_INNER * DT_RANK];       // 2048x64
__device__ float g_wout[(size_t)D_MODEL * D_INNER];      // 1024x2048
// split-K partials for x_proj: [slice][n][128]
__device__ float g_xpart[(size_t)XSPLIT * NROW * 128];

// ---------------------------------------------------------------------------
// low-level helpers
// ---------------------------------------------------------------------------
__device__ __forceinline__ uint32_t to_tf32(float f) {
    uint32_t u;
    asm("cvt.rna.tf32.f32 %0, %1;" : "=r"(u) : "f"(f));
    return u;
}
__device__ __forceinline__ float tf32r(float f) { return __uint_as_float(to_tf32(f)); }

__device__ __forceinline__ void mma_tf32(float* d, const uint32_t* a, const uint32_t* b) {
    asm volatile(
        "mma.sync.aligned.m16n8k8.row.col.f32.tf32.tf32.f32 "
        "{%0,%1,%2,%3}, {%4,%5,%6,%7}, {%8,%9}, {%0,%1,%2,%3};\n"
        : "+f"(d[0]), "+f"(d[1]), "+f"(d[2]), "+f"(d[3])
        : "r"(a[0]), "r"(a[1]), "r"(a[2]), "r"(a[3]), "r"(b[0]), "r"(b[1]));
}
__device__ __forceinline__ void ldsm4(uint32_t* r, uint32_t saddr) {
    asm volatile("ldmatrix.sync.aligned.m8n8.x4.shared.b16 {%0,%1,%2,%3}, [%4];"
                 : "=r"(r[0]), "=r"(r[1]), "=r"(r[2]), "=r"(r[3]) : "r"(saddr));
}
__device__ __forceinline__ void cp_async16(uint32_t dst, const void* src) {
    asm volatile("cp.async.cg.shared.global [%0], [%1], 16;" :: "r"(dst), "l"(src));
}
__device__ __forceinline__ void cp_commit() {
    asm volatile("cp.async.commit_group;" ::: "memory");
}
template<int N> __device__ __forceinline__ void cp_wait() {
    asm volatile("cp.async.wait_group %0;" :: "n"(N) : "memory");
}

// ---------------------------------------------------------------------------
// tf32 mma.sync GEMM with cp.async 3-stage pipeline + ldmatrix fragments.
//   Ct[n][m] = sum_k Act[n][k] * W[m][k]   (+ epilogue per MODE)
// MODE 0: plain   MODE 1: +R[n][m] residual   MODE 2: softplus(v + R[m])
// MODE 3: split-K partial -> Ct + blockIdx.z * (NROW*128), kStart = z*kLen
// 128x128 tile, K-chunk 32, 256 threads = 2(M-rows) x 4(features) warps,
// each warp 64x32 = 4x4 m16n8k8 tiles. smem rows stride 36 words.
// ---------------------------------------------------------------------------
#define ROW_STR   36
#define TILE_B    (128 * ROW_STR * 4)        // 18432 B per operand tile
#define STAGE_B   (2 * TILE_B)               // A + B per stage
#define GSMEM_BYTES (3 * STAGE_B)            // 110592 B

template<int MODE>
__global__ __launch_bounds__(256)
void gemm_mma(const float* __restrict__ W, int ldw, int kLen,
              const float* __restrict__ Act, int ldact,
              float* __restrict__ Ct, int ldc,
              const float* __restrict__ R) {
    extern __shared__ __align__(16) char smem[];
    const uint32_t sbase = (uint32_t)__cvta_generic_to_shared(smem);
    const int tid    = threadIdx.x;
    const int lane   = tid & 31;
    const int wid    = tid >> 5;
    const int qid    = lane >> 2;
    const int qtid   = lane & 3;
    const int warp_m = wid & 1;
    const int warp_n = wid >> 1;
    const int n0     = blockIdx.x * 128;
    const int m0     = blockIdx.y * 128;
    const int kStart = (MODE == 3) ? blockIdx.z * kLen : 0;
    if (MODE == 3) Ct += (size_t)blockIdx.z * NROW * 128;

    float acc[4][4][4];
#pragma unroll
    for (int mt = 0; mt < 4; mt++)
#pragma unroll
        for (int nt = 0; nt < 4; nt++)
#pragma unroll
            for (int q = 0; q < 4; q++) acc[mt][nt][q] = 0.0f;

    const int KI = kLen >> 5;

    // per-thread staging coordinates (4 rows each of A and B)
    const int srow = tid >> 1;                 // 0..127 row for jj pair step 2? (recomputed below)

    // stage(i, buf): copy chunk i of A(Act) and B(W) into stage buf
    auto stage = [&](int i, int buf) {
        const int k0 = kStart + (i << 5);
        const uint32_t sA = sbase + buf * STAGE_B;
        const uint32_t sB = sA + TILE_B;
#pragma unroll
        for (int jj = 0; jj < 4; jj++) {
            const int f   = jj * 256 + tid;
            const int row = f >> 3;
            const int kq  = (f & 7) * 4;
            cp_async16(sA + (uint32_t)(row * ROW_STR + kq) * 4,
                       Act + (size_t)(n0 + row) * ldact + k0 + kq);
            cp_async16(sB + (uint32_t)(row * ROW_STR + kq) * 4,
                       W + (size_t)(m0 + row) * ldw + k0 + kq);
        }
        cp_commit();
    };
    (void)srow;

    // fragment lane offsets (words)
    const uint32_t aOff = (uint32_t)((warp_m * 64 + (lane & 15)) * ROW_STR + (lane >> 4) * 4);
    const uint32_t bOff = (uint32_t)((warp_n * 32 + ((lane >> 4) & 1) * 8 + (lane & 7)) * ROW_STR
                                     + ((lane >> 3) & 1) * 4);

    // prologue
    stage(0, 0);
    if (KI > 1) stage(1, 1);

    for (int i = 0; i < KI; i++) {
        if (i + 1 < KI) cp_wait<1>(); else cp_wait<0>();
        __syncthreads();
        if (i + 2 < KI) stage(i + 2, (i + 2) % 3);

        const int buf = i % 3;
        const uint32_t aB = sbase + buf * STAGE_B;
        const uint32_t bB = aB + TILE_B;
#pragma unroll
        for (int ks = 0; ks < 4; ks++) {
            const uint32_t kb = ks * 8;
            uint32_t af[4][4], bf0[4], bf1[4];
#pragma unroll
            for (int mt = 0; mt < 4; mt++)
                ldsm4(af[mt], aB + (aOff + mt * 16 * ROW_STR + kb) * 4);
            ldsm4(bf0, bB + (bOff + kb) * 4);
            ldsm4(bf1, bB + (bOff + 16 * ROW_STR + kb) * 4);
            const uint32_t* bfr[4] = { &bf0[0], &bf0[2], &bf1[0], &bf1[2] };
#pragma unroll
            for (int mt = 0; mt < 4; mt++)
#pragma unroll
                for (int nt = 0; nt < 4; nt++)
                    mma_tf32(acc[mt][nt], af[mt], bfr[nt]);
        }
        __syncthreads();
    }

    // epilogue: Ct[n][m] float2 stores
#pragma unroll
    for (int mt = 0; mt < 4; mt++) {
        const int n = n0 + warp_m * 64 + mt * 16 + qid;
#pragma unroll
        for (int nt = 0; nt < 4; nt++) {
            const int m = m0 + warp_n * 32 + nt * 8 + 2 * qtid;
            float2 v0 = make_float2(acc[mt][nt][0], acc[mt][nt][1]);
            float2 v1 = make_float2(acc[mt][nt][2], acc[mt][nt][3]);
            if (MODE == 1) {
                const float2 r0 = *(const float2*)(R + (size_t)n * ldc + m);
                const float2 r1 = *(const float2*)(R + (size_t)(n + 8) * ldc + m);
                v0.x += r0.x; v0.y += r0.y;
                v1.x += r1.x; v1.y += r1.y;
            } else if (MODE == 2) {
                const float2 bb = *(const float2*)(R + m);
                v0.x += bb.x; v0.y += bb.y; v1.x += bb.x; v1.y += bb.y;
                v0.x = (v0.x > 20.0f) ? v0.x : log1pf(expf(v0.x));
                v0.y = (v0.y > 20.0f) ? v0.y : log1pf(expf(v0.y));
                v1.x = (v1.x > 20.0f) ? v1.x : log1pf(expf(v1.x));
                v1.y = (v1.y > 20.0f) ? v1.y : log1pf(expf(v1.y));
            }
            *(float2*)(Ct + (size_t)n * ldc + m) = v0;
            *(float2*)(Ct + (size_t)(n + 8) * ldc + m) = v1;
        }
    }
}

// ---------------------------------------------------------------------------
// Weight convert: dst[row][col] = tf32(src[row][col]) for row<rowsValid else 0.
// ---------------------------------------------------------------------------
__global__ void cvt_w_kernel(const float* __restrict__ src, float* __restrict__ dst,
                             int rowsValid, int cols, int total4) {
    const int i4 = blockIdx.x * 256 + threadIdx.x;
    if (i4 >= total4) return;
    const int i = i4 * 4;
    const int row = i / cols;
    float4 v = make_float4(0.f, 0.f, 0.f, 0.f);
    if (row < rowsValid) {
        v = *(const float4*)(src + i);
        v.x = tf32r(v.x); v.y = tf32r(v.y); v.z = tf32r(v.z); v.w = tf32r(v.w);
    }
    *(float4*)(dst + i) = v;
}

// ---------------------------------------------------------------------------
// x_proj split-K reduce: xdbl[n][m] = tf32(sum_s part[s][n][m]), m < 96
// ---------------------------------------------------------------------------
__global__ void reduce_x_kernel() {
    const int idx = blockIdx.x * 256 + threadIdx.x;   // over NROW*96
    if (idx >= NROW * XDBL_W) return;
    const int n = idx / XDBL_W;
    const int m = idx - n * XDBL_W;
    float s = 0.0f;
#pragma unroll
    for (int sl = 0; sl < XSPLIT; sl++)
        s += g_xpart[((size_t)sl * NROW + n) * 128 + m];
    g_xdbl[idx] = tf32r(s);
}

// ---------------------------------------------------------------------------
// LayerNorm: one block per row n; writes h[n][d] (tf32-rounded).
// ---------------------------------------------------------------------------
__global__ void ln_kernel(const float* __restrict__ x,
                          const float* __restrict__ gamma,
                          const float* __restrict__ beta) {
    const int row = blockIdx.x;
    const int tid = threadIdx.x;           // 256
    const float4 v = *(const float4*)(x + (size_t)row * D_MODEL + tid * 4);

    float s  = v.x + v.y + v.z + v.w;
    float sq = v.x * v.x + v.y * v.y + v.z * v.z + v.w * v.w;

    __shared__ float red_s[8], red_q[8];
    for (int o = 16; o > 0; o >>= 1) {
        s  += __shfl_xor_sync(0xffffffffu, s, o);
        sq += __shfl_xor_sync(0xffffffffu, sq, o);
    }
    const int wid = tid >> 5, lid = tid & 31;
    if (lid == 0) { red_s[wid] = s; red_q[wid] = sq; }
    __syncthreads();
    if (wid == 0) {
        s  = red_s[lid & 7];
        sq = red_q[lid & 7];
        for (int o = 4; o > 0; o >>= 1) {
            s  += __shfl_xor_sync(0xffffffffu, s, o);
            sq += __shfl_xor_sync(0xffffffffu, sq, o);
        }
        if (lid == 0) { red_s[0] = s; red_q[0] = sq; }
    }
    __syncthreads();
    const float mean = red_s[0] * (1.0f / D_MODEL);
    const float var  = red_q[0] * (1.0f / D_MODEL) - mean * mean;
    const float rstd = rsqrtf(var + 1e-6f);

    const int d0 = tid * 4;
    const float4 g4 = *(const float4*)(gamma + d0);
    const float4 b4 = *(const float4*)(beta + d0);
    float4 o4;
    o4.x = tf32r((v.x - mean) * rstd * g4.x + b4.x);
    o4.y = tf32r((v.y - mean) * rstd * g4.y + b4.y);
    o4.z = tf32r((v.z - mean) * rstd * g4.z + b4.z);
    o4.w = tf32r((v.w - mean) * rstd * g4.w + b4.w);
    *(float4*)(g_h + (size_t)row * D_MODEL + d0) = o4;
}

// ---------------------------------------------------------------------------
// Depthwise causal conv(k=4)+bias+SiLU. uct[n][d] tf32-rounded; ucl full fp32.
// ---------------------------------------------------------------------------
__global__ __launch_bounds__(256)
void conv_kernel(const float* __restrict__ conv_w,
                 const float* __restrict__ conv_b) {
    __shared__ float s_in[67][33];
    __shared__ float s_out[64][33];
    const int tid = threadIdx.x;
    const int d0  = blockIdx.x * 32;
    const int l0  = blockIdx.y * 64;
    const int b   = blockIdx.z;

    for (int base = tid; base < 67 * 32; base += 256) {
        const int r = base >> 5;
        const int c = base & 31;
        const int l = l0 - 3 + r;
        float v = 0.0f;
        if (l >= 0) v = g_xzT[((size_t)b * L_SEQ + l) * E2 + d0 + c];
        s_in[r][c] = v;
    }
    __syncthreads();

    for (int base = tid; base < 64 * 32; base += 256) {
        const int ll = base >> 5;
        const int c  = base & 31;
        const int d  = d0 + c;
        const float4 w = *(const float4*)(conv_w + d * 4);
        float s = conv_b[d];
        s = fmaf(w.x, s_in[ll + 0][c], s);
        s = fmaf(w.y, s_in[ll + 1][c], s);
        s = fmaf(w.z, s_in[ll + 2][c], s);
        s = fmaf(w.w, s_in[ll + 3][c], s);
        const float v = s / (1.0f + expf(-s));
        s_out[ll][c] = v;
        g_uct[((size_t)b * L_SEQ + l0 + ll) * D_INNER + d] = tf32r(v);
    }
    __syncthreads();

    const int ll = tid & 63;
    const int cg = tid >> 6;   // 0..3
#pragma unroll
    for (int j = 0; j < 8; j++) {
        const int c = cg * 8 + j;
        g_ucl[((size_t)b * D_INNER + d0 + c) * L_SEQ + l0 + ll] = s_out[ll][c];
    }
}

// ---------------------------------------------------------------------------
// Selective scan. Half-warp (16 lanes = 16 states) per channel d.
// delta pre-softplus'd, layout [n][d]. Writes yt[n][d] (pre-silu(z)).
// ---------------------------------------------------------------------------
__global__ __launch_bounds__(256)
void scan_kernel(const float* __restrict__ A_log,
                 const float* __restrict__ Dvec) {
    const int tid  = threadIdx.x;
    const int lane = tid & 31;
    const int n    = lane & 15;
    const int half = lane >> 4;
    const int w    = tid >> 5;
    const int d    = blockIdx.x * 16 + w * 2 + half;
    const int b    = blockIdx.y;

    const float An = -expf(A_log[d * D_STATE + n]);
    const float Dd = Dvec[d];

    const float* dp = g_deltaT + (size_t)b * L_SEQ * D_INNER + d;
    const float* up = g_ucl    + ((size_t)b * D_INNER + d) * L_SEQ;
    const float* xd = g_xdbl   + (size_t)b * L_SEQ * XDBL_W;
    float*       yp = g_yt     + (size_t)b * L_SEQ * D_INNER + d;

    float state = 0.0f;

#pragma unroll 4
    for (int l = 0; l < L_SEQ; l++) {
        const float dv = __ldg(dp + (size_t)l * D_INNER);
        const float u  = __ldg(up + l);
        const float Bn = __ldg(xd + (size_t)l * XDBL_W + DT_RANK + n);
        const float Cn = __ldg(xd + (size_t)l * XDBL_W + DT_RANK + D_STATE + n);

        const float dA = __expf(dv * An);
        state = fmaf(dA, state, dv * Bn * u);

        float yc = state * Cn;
        yc += __shfl_xor_sync(0xffffffffu, yc, 1);
        yc += __shfl_xor_sync(0xffffffffu, yc, 2);
        yc += __shfl_xor_sync(0xffffffffu, yc, 4);
        yc += __shfl_xor_sync(0xffffffffu, yc, 8);

        if (n == 0) {
            yp[(size_t)l * D_INNER] = yc + u * Dd;
        }
    }
}

// ---------------------------------------------------------------------------
// y = tf32(y * silu(z)) elementwise. yt[n][d], z = xzT[n][2048+d].
// ---------------------------------------------------------------------------
__global__ void ymult_kernel() {
    const size_t i = (size_t)blockIdx.x * 256 + threadIdx.x;
    const int nrow = (int)(i >> 9);
    const int d4   = ((int)i & 511) * 4;
    const float4 z4 = *(const float4*)(g_xzT + (size_t)nrow * E2 + D_INNER + d4);
    float4 y4 = *(float4*)(g_yt + (size_t)nrow * D_INNER + d4);
    y4.x = tf32r(y4.x * (z4.x / (1.0f + expf(-z4.x))));
    y4.y = tf32r(y4.y * (z4.y / (1.0f + expf(-z4.y))));
    y4.z = tf32r(y4.z * (z4.z / (1.0f + expf(-z4.z))));
    y4.w = tf32r(y4.w * (z4.w / (1.0f + expf(-z4.w))));
    *(float4*)(g_yt + (size_t)nrow * D_INNER + d4) = y4;
}

// ---------------------------------------------------------------------------
// Launch
// ---------------------------------------------------------------------------
extern "C" void kernel_launch(void* const* d_in, const int* in_sizes, int n_in,
                              void* d_out, int out_size) {
    const float* x        = (const float*)d_in[0];
    const float* ln_gamma = (const float*)d_in[1];
    const float* ln_beta  = (const float*)d_in[2];
    const float* in_proj  = (const float*)d_in[3];
    const float* conv_w   = (const float*)d_in[4];
    const float* conv_b   = (const float*)d_in[5];
    const float* x_proj   = (const float*)d_in[6];
    const float* dt_proj  = (const float*)d_in[7];
    const float* dt_pb    = (const float*)d_in[8];
    const float* A_log    = (const float*)d_in[9];
    const float* Dvec     = (const float*)d_in[10];
    const float* out_proj = (const float*)d_in[11];
    float* out = (float*)d_out;

    float *h, *uct, *xdbl, *deltaT, *yt, *xzT, *win, *wx, *wdt, *wout, *xpart;
    cudaGetSymbolAddress((void**)&h,      g_h);
    cudaGetSymbolAddress((void**)&xzT,    g_xzT);
    cudaGetSymbolAddress((void**)&uct,    g_uct);
    cudaGetSymbolAddress((void**)&xdbl,   g_xdbl);
    cudaGetSymbolAddress((void**)&deltaT, g_deltaT);
    cudaGetSymbolAddress((void**)&yt,     g_yt);
    cudaGetSymbolAddress((void**)&win,    g_win);
    cudaGetSymbolAddress((void**)&wx,     g_wx);
    cudaGetSymbolAddress((void**)&wdt,    g_wdt);
    cudaGetSymbolAddress((void**)&wout,   g_wout);
    cudaGetSymbolAddress((void**)&xpart,  g_xpart);

    static bool attr_set = false;
    if (!attr_set) {
        cudaFuncSetAttribute(gemm_mma<0>, cudaFuncAttributeMaxDynamicSharedMemorySize, GSMEM_BYTES);
        cudaFuncSetAttribute(gemm_mma<1>, cudaFuncAttributeMaxDynamicSharedMemorySize, GSMEM_BYTES);
        cudaFuncSetAttribute(gemm_mma<2>, cudaFuncAttributeMaxDynamicSharedMemorySize, GSMEM_BYTES);
        cudaFuncSetAttribute(gemm_mma<3>, cudaFuncAttributeMaxDynamicSharedMemorySize, GSMEM_BYTES);
        attr_set = true;
    }

    // 0. convert weights to tf32 (every launch; deterministic)
    {
        int t;
        t = E2 * D_MODEL / 4;
        cvt_w_kernel<<<(t + 255) / 256, 256>>>(in_proj, win, E2, D_MODEL, t);
        t = 128 * D_INNER / 4;
        cvt_w_kernel<<<(t + 255) / 256, 256>>>(x_proj, wx, XDBL_W, D_INNER, t);
        t = D_INNER * DT_RANK / 4;
        cvt_w_kernel<<<(t + 255) / 256, 256>>>(dt_proj, wdt, D_INNER, DT_RANK, t);
        t = D_MODEL * D_INNER / 4;
        cvt_w_kernel<<<(t + 255) / 256, 256>>>(out_proj, wout, D_MODEL, D_INNER, t);
    }

    // 1. LayerNorm -> h[n][d] (tf32)
    ln_kernel<<<NROW, 256>>>(x, ln_gamma, ln_beta);

    // 2. in_proj: xzT[n][e] = h[n][:] . Win[e][:]
    gemm_mma<0><<<dim3(NROW / 128, E2 / 128), 256, GSMEM_BYTES>>>(
        win, D_MODEL, D_MODEL, h, D_MODEL, xzT, E2, nullptr);

    // 3. conv + SiLU
    conv_kernel<<<dim3(D_INNER / 32, L_SEQ / 64, B_SZ), 256>>>(conv_w, conv_b);

    // 4. x_proj split-K partials, then reduce -> xdbl[n][96]
    gemm_mma<3><<<dim3(NROW / 128, 1, XSPLIT), 256, GSMEM_BYTES>>>(
        wx, D_INNER, D_INNER / XSPLIT, uct, D_INNER, xpart, 128, nullptr);
    reduce_x_kernel<<<(NROW * XDBL_W + 255) / 256, 256>>>();

    // 5. dt_proj (tensor) + bias + softplus -> deltaT[n][d]
    gemm_mma<2><<<dim3(NROW / 128, D_INNER / 128), 256, GSMEM_BYTES>>>(
        wdt, DT_RANK, DT_RANK, xdbl, XDBL_W, deltaT, D_INNER, dt_pb);

    // 6. selective scan -> yt[n][d]
    scan_kernel<<<dim3(D_INNER / 16, B_SZ), 256>>>(A_log, Dvec);

    // 7. y *= silu(z), round to tf32
    ymult_kernel<<<(NROW * D_INNER / 4) / 256, 256>>>();

    // 8. out_proj + residual: out[n][e] = yt[n][:] . Wout[e][:] + x
    gemm_mma<1><<<dim3(NROW / 128, D_MODEL / 128), 256, GSMEM_BYTES>>>(
        wout, D_INNER, D_INNER, yt, D_INNER, out, D_MODEL, x);
}

// round 12
// speedup vs baseline: 4.2639x; 1.2319x over previous
#include <cuda_runtime.h>
#include <cuda_bf16.h>
#include <math.h>
#include <stdint.h>

// ---------------------------------------------------------------------------
// Problem constants
// ---------------------------------------------------------------------------
#define B_SZ    2
#define L_SEQ   2048
#define D_MODEL 1024
#define D_INNER 2048
#define D_STATE 16
#define D_CONV  4
#define DT_RANK 64
#define NROW    (B_SZ * L_SEQ)           // 4096 rows n=(b,l)
#define E2      (2 * D_INNER)            // 4096
#define XDBL_W  (DT_RANK + 2 * D_STATE)  // 96
#define XSPLIT  4                        // split-K slices for x_proj

// ---------------------------------------------------------------------------
// Scratch (device globals; no cudaMalloc allowed)
// ---------------------------------------------------------------------------
__device__ __nv_bfloat16 g_h[(size_t)NROW * D_MODEL];       // LN out [n][d] bf16
__device__ float  g_xzT[(size_t)NROW * E2];                 // in_proj out [n][e] fp32
__device__ __nv_bfloat16 g_uct[(size_t)NROW * D_INNER];     // conv out [n][d] bf16
__device__ float  g_ucl[(size_t)B_SZ * D_INNER * L_SEQ];    // conv out [b][d][l] fp32
__device__ float  g_xdbl[(size_t)NROW * XDBL_W];            // x_proj out fp32 (scan input)
__device__ __nv_bfloat16 g_xdbl_bf[(size_t)NROW * XDBL_W];  // bf16 copy (dt GEMM operand)
__device__ float  g_deltaT[(size_t)NROW * D_INNER];         // softplus(dt) [n][d] fp32
__device__ float  g_ysc[(size_t)NROW * D_INNER];            // scan out [n][d] fp32
__device__ __nv_bfloat16 g_yt[(size_t)NROW * D_INNER];      // y*silu(z) [n][d] bf16
// bf16 weights (converted every launch)
__device__ __nv_bfloat16 g_win[(size_t)E2 * D_MODEL];
__device__ __nv_bfloat16 g_wx[(size_t)128 * D_INNER];       // 96 rows padded to 128
__device__ __nv_bfloat16 g_wdt[(size_t)D_INNER * DT_RANK];
__device__ __nv_bfloat16 g_wout[(size_t)D_MODEL * D_INNER];
// split-K partials for x_proj
__device__ float g_xpart[(size_t)XSPLIT * NROW * 128];

// ---------------------------------------------------------------------------
// low-level helpers
// ---------------------------------------------------------------------------
__device__ __forceinline__ void mma_bf16(float* d, const uint32_t* a, const uint32_t* b) {
    asm volatile(
        "mma.sync.aligned.m16n8k16.row.col.f32.bf16.bf16.f32 "
        "{%0,%1,%2,%3}, {%4,%5,%6,%7}, {%8,%9}, {%0,%1,%2,%3};\n"
        : "+f"(d[0]), "+f"(d[1]), "+f"(d[2]), "+f"(d[3])
        : "r"(a[0]), "r"(a[1]), "r"(a[2]), "r"(a[3]), "r"(b[0]), "r"(b[1]));
}
__device__ __forceinline__ void ldsm4(uint32_t* r, uint32_t saddr) {
    asm volatile("ldmatrix.sync.aligned.m8n8.x4.shared.b16 {%0,%1,%2,%3}, [%4];"
                 : "=r"(r[0]), "=r"(r[1]), "=r"(r[2]), "=r"(r[3]) : "r"(saddr));
}
__device__ __forceinline__ void cp_async16(uint32_t dst, const void* src) {
    asm volatile("cp.async.cg.shared.global [%0], [%1], 16;" :: "r"(dst), "l"(src));
}
__device__ __forceinline__ void cp_commit() {
    asm volatile("cp.async.commit_group;" ::: "memory");
}
template<int N> __device__ __forceinline__ void cp_wait() {
    asm volatile("cp.async.wait_group %0;" :: "n"(N) : "memory");
}

// ---------------------------------------------------------------------------
// bf16 mma.sync GEMM, cp.async 3-stage pipeline + ldmatrix fragments.
//   Ct[n][m] = sum_k Act[n][k] * W[m][k]   (+ epilogue per MODE)
// MODE 0: plain   MODE 1: +R[n][m]   MODE 2: softplus(v + R[m])
// MODE 3: split-K partial -> Ct + z*(NROW*128), kStart = z*kLen
// 128x128 tile, K-chunk 32 (bf16), 256 threads = 2(M) x 4(N) warps,
// warp tile 64x32 = 4x4 m16n8k16 tiles x 2 k-steps.
// smem rows: 32 bf16 = 64B, stride 80B (conflict-free ldmatrix phases).
// ---------------------------------------------------------------------------
#define RS_B      80
#define TILE_B    (128 * RS_B)          // 10240 B per operand tile
#define STAGE_B   (2 * TILE_B)          // 20480 B per stage
#define GSMEM_BYTES (3 * STAGE_B)       // 61440 B

template<int MODE>
__global__ __launch_bounds__(256, 2)
void gemm_bf(const __nv_bfloat16* __restrict__ W, int ldw, int kLen,
             const __nv_bfloat16* __restrict__ Act, int ldact,
             float* __restrict__ Ct, int ldc,
             const float* __restrict__ R) {
    extern __shared__ __align__(16) char smem[];
    const uint32_t sbase = (uint32_t)__cvta_generic_to_shared(smem);
    const int tid    = threadIdx.x;
    const int lane   = tid & 31;
    const int wid    = tid >> 5;
    const int qid    = lane >> 2;
    const int qtid   = lane & 3;
    const int warp_m = wid & 1;
    const int warp_n = wid >> 1;
    const int n0     = blockIdx.x * 128;
    const int m0     = blockIdx.y * 128;
    const int kStart = (MODE == 3) ? blockIdx.z * kLen : 0;
    if (MODE == 3) Ct += (size_t)blockIdx.z * NROW * 128;

    float acc[4][4][4];
#pragma unroll
    for (int mt = 0; mt < 4; mt++)
#pragma unroll
        for (int nt = 0; nt < 4; nt++)
#pragma unroll
            for (int q = 0; q < 4; q++) acc[mt][nt][q] = 0.0f;

    const int KI = kLen >> 5;

    auto stage = [&](int i, int buf) {
        const int k0 = kStart + (i << 5);
        const uint32_t sA = sbase + buf * STAGE_B;
        const uint32_t sB = sA + TILE_B;
#pragma unroll
        for (int jj = 0; jj < 2; jj++) {
            const int f   = jj * 256 + tid;
            const int row = f >> 2;
            const int seg = f & 3;
            cp_async16(sA + (uint32_t)(row * RS_B + seg * 16),
                       Act + (size_t)(n0 + row) * ldact + k0 + seg * 8);
            cp_async16(sB + (uint32_t)(row * RS_B + seg * 16),
                       W + (size_t)(m0 + row) * ldw + k0 + seg * 8);
        }
        cp_commit();
    };

    // ldmatrix lane offsets (bytes)
    const uint32_t aOff = (uint32_t)((warp_m * 64 + (lane & 7) + ((lane >> 3) & 1) * 8) * RS_B
                                     + (lane >> 4) * 16);
    const uint32_t bOff = (uint32_t)((warp_n * 32 + (lane & 7) + ((lane >> 4) & 1) * 8) * RS_B
                                     + ((lane >> 3) & 1) * 16);

    stage(0, 0);
    if (KI > 1) stage(1, 1);

    for (int i = 0; i < KI; i++) {
        if (i + 1 < KI) cp_wait<1>(); else cp_wait<0>();
        __syncthreads();
        if (i + 2 < KI) stage(i + 2, (i + 2) % 3);

        const uint32_t aB = sbase + (i % 3) * STAGE_B;
        const uint32_t bB = aB + TILE_B;
#pragma unroll
        for (int ks = 0; ks < 2; ks++) {
            uint32_t af[4][4], bp0[4], bp1[4];
#pragma unroll
            for (int mt = 0; mt < 4; mt++)
                ldsm4(af[mt], aB + aOff + (uint32_t)(mt * 16 * RS_B + ks * 32));
            ldsm4(bp0, bB + bOff + (uint32_t)(ks * 32));
            ldsm4(bp1, bB + bOff + (uint32_t)(16 * RS_B + ks * 32));
            const uint32_t* bfr[4] = { &bp0[0], &bp0[2], &bp1[0], &bp1[2] };
#pragma unroll
            for (int mt = 0; mt < 4; mt++)
#pragma unroll
                for (int nt = 0; nt < 4; nt++)
                    mma_bf16(acc[mt][nt], af[mt], bfr[nt]);
        }
        __syncthreads();
    }

    // epilogue: Ct[n][m] float2 stores
#pragma unroll
    for (int mt = 0; mt < 4; mt++) {
        const int n = n0 + warp_m * 64 + mt * 16 + qid;
#pragma unroll
        for (int nt = 0; nt < 4; nt++) {
            const int m = m0 + warp_n * 32 + nt * 8 + 2 * qtid;
            float2 v0 = make_float2(acc[mt][nt][0], acc[mt][nt][1]);
            float2 v1 = make_float2(acc[mt][nt][2], acc[mt][nt][3]);
            if (MODE == 1) {
                const float2 r0 = *(const float2*)(R + (size_t)n * ldc + m);
                const float2 r1 = *(const float2*)(R + (size_t)(n + 8) * ldc + m);
                v0.x += r0.x; v0.y += r0.y;
                v1.x += r1.x; v1.y += r1.y;
            } else if (MODE == 2) {
                const float2 bb = *(const float2*)(R + m);
                v0.x += bb.x; v0.y += bb.y; v1.x += bb.x; v1.y += bb.y;
                v0.x = (v0.x > 20.0f) ? v0.x : log1pf(expf(v0.x));
                v0.y = (v0.y > 20.0f) ? v0.y : log1pf(expf(v0.y));
                v1.x = (v1.x > 20.0f) ? v1.x : log1pf(expf(v1.x));
                v1.y = (v1.y > 20.0f) ? v1.y : log1pf(expf(v1.y));
            }
            *(float2*)(Ct + (size_t)n * ldc + m) = v0;
            *(float2*)(Ct + (size_t)(n + 8) * ldc + m) = v1;
        }
    }
}

// ---------------------------------------------------------------------------
// Weight convert fp32 -> bf16, zero-pad rows >= rowsValid.
// ---------------------------------------------------------------------------
__global__ void cvt_w_kernel(const float* __restrict__ src, __nv_bfloat16* __restrict__ dst,
                             int rowsValid, int cols, int total4) {
    const int i4 = blockIdx.x * 256 + threadIdx.x;
    if (i4 >= total4) return;
    const int i = i4 * 4;
    const int row = i / cols;
    float4 v = make_float4(0.f, 0.f, 0.f, 0.f);
    if (row < rowsValid) v = *(const float4*)(src + i);
    __nv_bfloat162 p01 = __floats2bfloat162_rn(v.x, v.y);
    __nv_bfloat162 p23 = __floats2bfloat162_rn(v.z, v.w);
    uint2 u = make_uint2(*(uint32_t*)&p01, *(uint32_t*)&p23);
    *(uint2*)(dst + i) = u;
}

// ---------------------------------------------------------------------------
// x_proj split-K reduce: fp32 xdbl (scan input) + bf16 copy (dt operand).
// ---------------------------------------------------------------------------
__global__ void reduce_x_kernel() {
    const int idx = blockIdx.x * 256 + threadIdx.x;   // over NROW*96
    if (idx >= NROW * XDBL_W) return;
    const int n = idx / XDBL_W;
    const int m = idx - n * XDBL_W;
    float s = 0.0f;
#pragma unroll
    for (int sl = 0; sl < XSPLIT; sl++)
        s += g_xpart[((size_t)sl * NROW + n) * 128 + m];
    g_xdbl[idx]    = s;
    g_xdbl_bf[idx] = __float2bfloat16_rn(s);
}

// ---------------------------------------------------------------------------
// LayerNorm: one block per row n; writes h[n][d] bf16.
// ---------------------------------------------------------------------------
__global__ void ln_kernel(const float* __restrict__ x,
                          const float* __restrict__ gamma,
                          const float* __restrict__ beta) {
    const int row = blockIdx.x;
    const int tid = threadIdx.x;           // 256
    const float4 v = *(const float4*)(x + (size_t)row * D_MODEL + tid * 4);

    float s  = v.x + v.y + v.z + v.w;
    float sq = v.x * v.x + v.y * v.y + v.z * v.z + v.w * v.w;

    __shared__ float red_s[8], red_q[8];
    for (int o = 16; o > 0; o >>= 1) {
        s  += __shfl_xor_sync(0xffffffffu, s, o);
        sq += __shfl_xor_sync(0xffffffffu, sq, o);
    }
    const int wid = tid >> 5, lid = tid & 31;
    if (lid == 0) { red_s[wid] = s; red_q[wid] = sq; }
    __syncthreads();
    if (wid == 0) {
        s  = red_s[lid & 7];
        sq = red_q[lid & 7];
        for (int o = 4; o > 0; o >>= 1) {
            s  += __shfl_xor_sync(0xffffffffu, s, o);
            sq += __shfl_xor_sync(0xffffffffu, sq, o);
        }
        if (lid == 0) { red_s[0] = s; red_q[0] = sq; }
    }
    __syncthreads();
    const float mean = red_s[0] * (1.0f / D_MODEL);
    const float var  = red_q[0] * (1.0f / D_MODEL) - mean * mean;
    const float rstd = rsqrtf(var + 1e-6f);

    const int d0 = tid * 4;
    const float4 g4 = *(const float4*)(gamma + d0);
    const float4 b4 = *(const float4*)(beta + d0);
    const float o0 = (v.x - mean) * rstd * g4.x + b4.x;
    const float o1 = (v.y - mean) * rstd * g4.y + b4.y;
    const float o2 = (v.z - mean) * rstd * g4.z + b4.z;
    const float o3 = (v.w - mean) * rstd * g4.w + b4.w;
    __nv_bfloat162 p01 = __floats2bfloat162_rn(o0, o1);
    __nv_bfloat162 p23 = __floats2bfloat162_rn(o2, o3);
    uint2 u = make_uint2(*(uint32_t*)&p01, *(uint32_t*)&p23);
    *(uint2*)(g_h + (size_t)row * D_MODEL + d0) = u;
}

// ---------------------------------------------------------------------------
// Depthwise causal conv(k=4)+bias+SiLU. uct bf16 [n][d]; ucl fp32 [b][d][l].
// ---------------------------------------------------------------------------
__global__ __launch_bounds__(256)
void conv_kernel(const float* __restrict__ conv_w,
                 const float* __restrict__ conv_b) {
    __shared__ float s_in[67][33];
    __shared__ float s_out[64][33];
    const int tid = threadIdx.x;
    const int d0  = blockIdx.x * 32;
    const int l0  = blockIdx.y * 64;
    const int b   = blockIdx.z;

    for (int base = tid; base < 67 * 32; base += 256) {
        const int r = base >> 5;
        const int c = base & 31;
        const int l = l0 - 3 + r;
        float v = 0.0f;
        if (l >= 0) v = g_xzT[((size_t)b * L_SEQ + l) * E2 + d0 + c];
        s_in[r][c] = v;
    }
    __syncthreads();

    for (int base = tid; base < 64 * 32; base += 256) {
        const int ll = base >> 5;
        const int c  = base & 31;
        const int d  = d0 + c;
        const float4 w = *(const float4*)(conv_w + d * 4);
        float s = conv_b[d];
        s = fmaf(w.x, s_in[ll + 0][c], s);
        s = fmaf(w.y, s_in[ll + 1][c], s);
        s = fmaf(w.z, s_in[ll + 2][c], s);
        s = fmaf(w.w, s_in[ll + 3][c], s);
        const float v = s / (1.0f + expf(-s));
        s_out[ll][c] = v;
        g_uct[((size_t)b * L_SEQ + l0 + ll) * D_INNER + d] = __float2bfloat16_rn(v);
    }
    __syncthreads();

    const int ll = tid & 63;
    const int cg = tid >> 6;   // 0..3
#pragma unroll
    for (int j = 0; j < 8; j++) {
        const int c = cg * 8 + j;
        g_ucl[((size_t)b * D_INNER + d0 + c) * L_SEQ + l0 + ll] = s_out[ll][c];
    }
}

// ---------------------------------------------------------------------------
// Selective scan. Half-warp (16 lanes = 16 states) per channel d.
// All inputs fp32. Writes ysc[n][d] fp32 (pre-silu(z)).
// ---------------------------------------------------------------------------
__global__ __launch_bounds__(256)
void scan_kernel(const float* __restrict__ A_log,
                 const float* __restrict__ Dvec) {
    const int tid  = threadIdx.x;
    const int lane = tid & 31;
    const int n    = lane & 15;
    const int half = lane >> 4;
    const int w    = tid >> 5;
    const int d    = blockIdx.x * 16 + w * 2 + half;
    const int b    = blockIdx.y;

    const float An = -expf(A_log[d * D_STATE + n]);
    const float Dd = Dvec[d];

    const float* dp = g_deltaT + (size_t)b * L_SEQ * D_INNER + d;
    const float* up = g_ucl    + ((size_t)b * D_INNER + d) * L_SEQ;
    const float* xd = g_xdbl   + (size_t)b * L_SEQ * XDBL_W;
    float*       yp = g_ysc    + (size_t)b * L_SEQ * D_INNER + d;

    float state = 0.0f;

#pragma unroll 4
    for (int l = 0; l < L_SEQ; l++) {
        const float dv = __ldg(dp + (size_t)l * D_INNER);
        const float u  = __ldg(up + l);
        const float Bn = __ldg(xd + (size_t)l * XDBL_W + DT_RANK + n);
        const float Cn = __ldg(xd + (size_t)l * XDBL_W + DT_RANK + D_STATE + n);

        const float dA = __expf(dv * An);
        state = fmaf(dA, state, dv * Bn * u);

        float yc = state * Cn;
        yc += __shfl_xor_sync(0xffffffffu, yc, 1);
        yc += __shfl_xor_sync(0xffffffffu, yc, 2);
        yc += __shfl_xor_sync(0xffffffffu, yc, 4);
        yc += __shfl_xor_sync(0xffffffffu, yc, 8);

        if (n == 0) {
            yp[(size_t)l * D_INNER] = yc + u * Dd;
        }
    }
}

// ---------------------------------------------------------------------------
// yt = bf16(ysc * silu(z)).  z = xzT[n][2048+d].
// ---------------------------------------------------------------------------
__global__ void ymult_kernel() {
    const size_t i = (size_t)blockIdx.x * 256 + threadIdx.x;
    const int nrow = (int)(i >> 9);
    const int d4   = ((int)i & 511) * 4;
    const float4 z4 = *(const float4*)(g_xzT + (size_t)nrow * E2 + D_INNER + d4);
    const float4 y4 = *(const float4*)(g_ysc + (size_t)nrow * D_INNER + d4);
    const float r0 = y4.x * (z4.x / (1.0f + expf(-z4.x)));
    const float r1 = y4.y * (z4.y / (1.0f + expf(-z4.y)));
    const float r2 = y4.z * (z4.z / (1.0f + expf(-z4.z)));
    const float r3 = y4.w * (z4.w / (1.0f + expf(-z4.w)));
    __nv_bfloat162 p01 = __floats2bfloat162_rn(r0, r1);
    __nv_bfloat162 p23 = __floats2bfloat162_rn(r2, r3);
    uint2 u = make_uint2(*(uint32_t*)&p01, *(uint32_t*)&p23);
    *(uint2*)(g_yt + (size_t)nrow * D_INNER + d4) = u;
}

// ---------------------------------------------------------------------------
// Launch
// ---------------------------------------------------------------------------
extern "C" void kernel_launch(void* const* d_in, const int* in_sizes, int n_in,
                              void* d_out, int out_size) {
    const float* x        = (const float*)d_in[0];
    const float* ln_gamma = (const float*)d_in[1];
    const float* ln_beta  = (const float*)d_in[2];
    const float* in_proj  = (const float*)d_in[3];
    const float* conv_w   = (const float*)d_in[4];
    const float* conv_b   = (const float*)d_in[5];
    const float* x_proj   = (const float*)d_in[6];
    const float* dt_proj  = (const float*)d_in[7];
    const float* dt_pb    = (const float*)d_in[8];
    const float* A_log    = (const float*)d_in[9];
    const float* Dvec     = (const float*)d_in[10];
    const float* out_proj = (const float*)d_in[11];
    float* out = (float*)d_out;

    float *xzT, *deltaT, *xpart, *xdbl;
    __nv_bfloat16 *h, *uct, *yt, *win, *wx, *wdt, *wout, *xdbl_bf;
    cudaGetSymbolAddress((void**)&h,       g_h);
    cudaGetSymbolAddress((void**)&xzT,     g_xzT);
    cudaGetSymbolAddress((void**)&uct,     g_uct);
    cudaGetSymbolAddress((void**)&xdbl,    g_xdbl);
    cudaGetSymbolAddress((void**)&xdbl_bf, g_xdbl_bf);
    cudaGetSymbolAddress((void**)&deltaT,  g_deltaT);
    cudaGetSymbolAddress((void**)&yt,      g_yt);
    cudaGetSymbolAddress((void**)&win,     g_win);
    cudaGetSymbolAddress((void**)&wx,      g_wx);
    cudaGetSymbolAddress((void**)&wdt,     g_wdt);
    cudaGetSymbolAddress((void**)&wout,    g_wout);
    cudaGetSymbolAddress((void**)&xpart,   g_xpart);

    static bool attr_set = false;
    if (!attr_set) {
        cudaFuncSetAttribute(gemm_bf<0>, cudaFuncAttributeMaxDynamicSharedMemorySize, GSMEM_BYTES);
        cudaFuncSetAttribute(gemm_bf<1>, cudaFuncAttributeMaxDynamicSharedMemorySize, GSMEM_BYTES);
        cudaFuncSetAttribute(gemm_bf<2>, cudaFuncAttributeMaxDynamicSharedMemorySize, GSMEM_BYTES);
        cudaFuncSetAttribute(gemm_bf<3>, cudaFuncAttributeMaxDynamicSharedMemorySize, GSMEM_BYTES);
        attr_set = true;
    }

    // 0. convert weights to bf16
    {
        int t;
        t = E2 * D_MODEL / 4;
        cvt_w_kernel<<<(t + 255) / 256, 256>>>(in_proj, win, E2, D_MODEL, t);
        t = 128 * D_INNER / 4;
        cvt_w_kernel<<<(t + 255) / 256, 256>>>(x_proj, wx, XDBL_W, D_INNER, t);
        t = D_INNER * DT_RANK / 4;
        cvt_w_kernel<<<(t + 255) / 256, 256>>>(dt_proj, wdt, D_INNER, DT_RANK, t);
        t = D_MODEL * D_INNER / 4;
        cvt_w_kernel<<<(t + 255) / 256, 256>>>(out_proj, wout, D_MODEL, D_INNER, t);
    }

    // 1. LayerNorm -> h[n][d] bf16
    ln_kernel<<<NROW, 256>>>(x, ln_gamma, ln_beta);

    // 2. in_proj: xzT[n][e] = h[n][:] . Win[e][:]
    gemm_bf<0><<<dim3(NROW / 128, E2 / 128), 256, GSMEM_BYTES>>>(
        win, D_MODEL, D_MODEL, h, D_MODEL, xzT, E2, nullptr);

    // 3. conv + SiLU
    conv_kernel<<<dim3(D_INNER / 32, L_SEQ / 64, B_SZ), 256>>>(conv_w, conv_b);

    // 4. x_proj split-K partials, then reduce -> xdbl (fp32 + bf16)
    gemm_bf<3><<<dim3(NROW / 128, 1, XSPLIT), 256, GSMEM_BYTES>>>(
        wx, D_INNER, D_INNER / XSPLIT, uct, D_INNER, xpart, 128, nullptr);
    reduce_x_kernel<<<(NROW * XDBL_W + 255) / 256, 256>>>();

    // 5. dt_proj (tensor) + bias + softplus -> deltaT[n][d] fp32
    gemm_bf<2><<<dim3(NROW / 128, D_INNER / 128), 256, GSMEM_BYTES>>>(
        wdt, DT_RANK, DT_RANK, xdbl_bf, XDBL_W, deltaT, D_INNER, dt_pb);

    // 6. selective scan -> ysc[n][d] fp32
    scan_kernel<<<dim3(D_INNER / 16, B_SZ), 256>>>(A_log, Dvec);

    // 7. yt = bf16(ysc * silu(z))
    ymult_kernel<<<(NROW * D_INNER / 4) / 256, 256>>>();

    // 8. out_proj + residual: out[n][e] = yt[n][:] . Wout[e][:] + x
    gemm_bf<1><<<dim3(NROW / 128, D_MODEL / 128), 256, GSMEM_BYTES>>>(
        wout, D_INNER, D_INNER, yt, D_INNER, out, D_MODEL, x);
}

// round 13
// speedup vs baseline: 4.2876x; 1.0056x over previous
#include <cuda_runtime.h>
#include <cuda_bf16.h>
#include <math.h>
#include <stdint.h>

// ---------------------------------------------------------------------------
// Problem constants
// ---------------------------------------------------------------------------
#define B_SZ    2
#define L_SEQ   2048
#define D_MODEL 1024
#define D_INNER 2048
#define D_STATE 16
#define D_CONV  4
#define DT_RANK 64
#define NROW    (B_SZ * L_SEQ)           // 4096 rows n=(b,l)
#define E2      (2 * D_INNER)            // 4096
#define XDBL_W  (DT_RANK + 2 * D_STATE)  // 96
#define XSPLIT  8                        // split-K slices for x_proj

// ---------------------------------------------------------------------------
// Scratch (device globals; no cudaMalloc allowed)
// ---------------------------------------------------------------------------
__device__ __nv_bfloat16 g_h[(size_t)NROW * D_MODEL];       // LN out [n][d] bf16
__device__ float  g_xzT[(size_t)NROW * E2];                 // in_proj out [n][e] fp32
__device__ __nv_bfloat16 g_uct[(size_t)NROW * D_INNER];     // conv out [n][d] bf16
__device__ float  g_ucl[(size_t)B_SZ * D_INNER * L_SEQ];    // conv out [b][d][l] fp32
__device__ float  g_xdbl[(size_t)NROW * XDBL_W];            // x_proj out fp32 (scan input)
__device__ __nv_bfloat16 g_xdbl_bf[(size_t)NROW * XDBL_W];  // bf16 copy (dt GEMM operand)
__device__ float  g_deltaT[(size_t)NROW * D_INNER];         // softplus(dt) [n][d] fp32
__device__ float  g_ysc[(size_t)NROW * D_INNER];            // scan out [n][d] fp32
__device__ __nv_bfloat16 g_yt[(size_t)NROW * D_INNER];      // y*silu(z) [n][d] bf16
// bf16 weights (converted every launch)
__device__ __nv_bfloat16 g_win[(size_t)E2 * D_MODEL];
__device__ __nv_bfloat16 g_wx[(size_t)128 * D_INNER];       // 96 rows padded to 128
__device__ __nv_bfloat16 g_wdt[(size_t)D_INNER * DT_RANK];
__device__ __nv_bfloat16 g_wout[(size_t)D_MODEL * D_INNER];
// split-K partials for x_proj
__device__ float g_xpart[(size_t)XSPLIT * NROW * 128];

// ---------------------------------------------------------------------------
// low-level helpers
// ---------------------------------------------------------------------------
__device__ __forceinline__ void mma_bf16(float* d, const uint32_t* a, const uint32_t* b) {
    asm volatile(
        "mma.sync.aligned.m16n8k16.row.col.f32.bf16.bf16.f32 "
        "{%0,%1,%2,%3}, {%4,%5,%6,%7}, {%8,%9}, {%0,%1,%2,%3};\n"
        : "+f"(d[0]), "+f"(d[1]), "+f"(d[2]), "+f"(d[3])
        : "r"(a[0]), "r"(a[1]), "r"(a[2]), "r"(a[3]), "r"(b[0]), "r"(b[1]));
}
__device__ __forceinline__ void ldsm4(uint32_t* r, uint32_t saddr) {
    asm volatile("ldmatrix.sync.aligned.m8n8.x4.shared.b16 {%0,%1,%2,%3}, [%4];"
                 : "=r"(r[0]), "=r"(r[1]), "=r"(r[2]), "=r"(r[3]) : "r"(saddr));
}
__device__ __forceinline__ void cp_async16(uint32_t dst, const void* src) {
    asm volatile("cp.async.cg.shared.global [%0], [%1], 16;" :: "r"(dst), "l"(src));
}
__device__ __forceinline__ void cp_commit() {
    asm volatile("cp.async.commit_group;" ::: "memory");
}
template<int N> __device__ __forceinline__ void cp_wait() {
    asm volatile("cp.async.wait_group %0;" :: "n"(N) : "memory");
}

// ---------------------------------------------------------------------------
// bf16 mma.sync GEMM, cp.async 4-stage pipeline + ldmatrix fragments.
//   Ct[n][m] = sum_k Act[n][k] * W[m][k]   (+ epilogue per MODE)
// MODE 0: plain   MODE 1: +R[n][m]   MODE 2: softplus(v + R[m])
// MODE 3: split-K partial -> Ct + z*(NROW*128), kStart = z*kLen
// CTA tile 128(n) x 128(m), K-chunk 32 (bf16), 128 threads = 2(n) x 2(m)
// warps; warp tile 64x64 = 4x8 m16n8k16 tiles x 2 k-steps.
// smem rows: 32 bf16 = 64B, stride 80B (conflict-free ldmatrix phases).
// ---------------------------------------------------------------------------
#define RS_B      80
#define TILE_B    (128 * RS_B)          // 10240 B per operand tile
#define STAGE_B   (2 * TILE_B)          // 20480 B per stage
#define GSMEM_BYTES (4 * STAGE_B)       // 81920 B (4 stages)

template<int MODE>
__global__ __launch_bounds__(128, 2)
void gemm_bf(const __nv_bfloat16* __restrict__ W, int ldw, int kLen,
             const __nv_bfloat16* __restrict__ Act, int ldact,
             float* __restrict__ Ct, int ldc,
             const float* __restrict__ R) {
    extern __shared__ __align__(16) char smem[];
    const uint32_t sbase = (uint32_t)__cvta_generic_to_shared(smem);
    const int tid    = threadIdx.x;
    const int lane   = tid & 31;
    const int wid    = tid >> 5;
    const int qid    = lane >> 2;
    const int qtid   = lane & 3;
    const int warp_m = wid & 1;      // act-row half (64 rows)
    const int warp_n = wid >> 1;     // feature half (64 feats)
    const int n0     = blockIdx.x * 128;
    const int m0     = blockIdx.y * 128;
    const int kStart = (MODE == 3) ? blockIdx.z * kLen : 0;
    if (MODE == 3) Ct += (size_t)blockIdx.z * NROW * 128;

    float acc[4][8][4];
#pragma unroll
    for (int mt = 0; mt < 4; mt++)
#pragma unroll
        for (int nt = 0; nt < 8; nt++)
#pragma unroll
            for (int q = 0; q < 4; q++) acc[mt][nt][q] = 0.0f;

    const int KI = kLen >> 5;

    auto stage = [&](int i, int buf) {
        const int k0 = kStart + (i << 5);
        const uint32_t sA = sbase + buf * STAGE_B;
        const uint32_t sB = sA + TILE_B;
#pragma unroll
        for (int jj = 0; jj < 4; jj++) {
            const int f   = jj * 128 + tid;
            const int row = f >> 2;
            const int seg = f & 3;
            cp_async16(sA + (uint32_t)(row * RS_B + seg * 16),
                       Act + (size_t)(n0 + row) * ldact + k0 + seg * 8);
            cp_async16(sB + (uint32_t)(row * RS_B + seg * 16),
                       W + (size_t)(m0 + row) * ldw + k0 + seg * 8);
        }
        cp_commit();
    };

    // ldmatrix lane offsets (bytes)
    const uint32_t aOff = (uint32_t)((warp_m * 64 + (lane & 7) + ((lane >> 3) & 1) * 8) * RS_B
                                     + (lane >> 4) * 16);
    const uint32_t bOff = (uint32_t)((warp_n * 64 + (lane & 7) + ((lane >> 4) & 1) * 8) * RS_B
                                     + ((lane >> 3) & 1) * 16);

    stage(0, 0);
    if (KI > 1) stage(1, 1);
    if (KI > 2) stage(2, 2);

    for (int i = 0; i < KI; i++) {
        if (i + 2 < KI)      cp_wait<2>();
        else if (i + 1 < KI) cp_wait<1>();
        else                 cp_wait<0>();
        __syncthreads();
        if (i + 3 < KI) stage(i + 3, (i + 3) & 3);

        const uint32_t aB = sbase + (i & 3) * STAGE_B;
        const uint32_t bB = aB + TILE_B;
#pragma unroll
        for (int ks = 0; ks < 2; ks++) {
            uint32_t af[4][4], bp[4][4];
#pragma unroll
            for (int mt = 0; mt < 4; mt++)
                ldsm4(af[mt], aB + aOff + (uint32_t)(mt * 16 * RS_B + ks * 32));
#pragma unroll
            for (int j = 0; j < 4; j++)
                ldsm4(bp[j], bB + bOff + (uint32_t)(j * 16 * RS_B + ks * 32));
#pragma unroll
            for (int mt = 0; mt < 4; mt++)
#pragma unroll
                for (int j = 0; j < 4; j++) {
                    mma_bf16(acc[mt][2 * j + 0], af[mt], &bp[j][0]);
                    mma_bf16(acc[mt][2 * j + 1], af[mt], &bp[j][2]);
                }
        }
        __syncthreads();
    }

    // epilogue: Ct[n][m] float2 stores
#pragma unroll
    for (int mt = 0; mt < 4; mt++) {
        const int n = n0 + warp_m * 64 + mt * 16 + qid;
#pragma unroll
        for (int nt = 0; nt < 8; nt++) {
            const int m = m0 + warp_n * 64 + nt * 8 + 2 * qtid;
            float2 v0 = make_float2(acc[mt][nt][0], acc[mt][nt][1]);
            float2 v1 = make_float2(acc[mt][nt][2], acc[mt][nt][3]);
            if (MODE == 1) {
                const float2 r0 = *(const float2*)(R + (size_t)n * ldc + m);
                const float2 r1 = *(const float2*)(R + (size_t)(n + 8) * ldc + m);
                v0.x += r0.x; v0.y += r0.y;
                v1.x += r1.x; v1.y += r1.y;
            } else if (MODE == 2) {
                const float2 bb = *(const float2*)(R + m);
                v0.x += bb.x; v0.y += bb.y; v1.x += bb.x; v1.y += bb.y;
                v0.x = (v0.x > 20.0f) ? v0.x : log1pf(expf(v0.x));
                v0.y = (v0.y > 20.0f) ? v0.y : log1pf(expf(v0.y));
                v1.x = (v1.x > 20.0f) ? v1.x : log1pf(expf(v1.x));
                v1.y = (v1.y > 20.0f) ? v1.y : log1pf(expf(v1.y));
            }
            *(float2*)(Ct + (size_t)n * ldc + m) = v0;
            *(float2*)(Ct + (size_t)(n + 8) * ldc + m) = v1;
        }
    }
}

// ---------------------------------------------------------------------------
// Weight convert fp32 -> bf16, zero-pad rows >= rowsValid.
// ---------------------------------------------------------------------------
__global__ void cvt_w_kernel(const float* __restrict__ src, __nv_bfloat16* __restrict__ dst,
                             int rowsValid, int cols, int total4) {
    const int i4 = blockIdx.x * 256 + threadIdx.x;
    if (i4 >= total4) return;
    const int i = i4 * 4;
    const int row = i / cols;
    float4 v = make_float4(0.f, 0.f, 0.f, 0.f);
    if (row < rowsValid) v = *(const float4*)(src + i);
    __nv_bfloat162 p01 = __floats2bfloat162_rn(v.x, v.y);
    __nv_bfloat162 p23 = __floats2bfloat162_rn(v.z, v.w);
    uint2 u = make_uint2(*(uint32_t*)&p01, *(uint32_t*)&p23);
    *(uint2*)(dst + i) = u;
}

// ---------------------------------------------------------------------------
// x_proj split-K reduce: fp32 xdbl (scan input) + bf16 copy (dt operand).
// ---------------------------------------------------------------------------
__global__ void reduce_x_kernel() {
    const int idx = blockIdx.x * 256 + threadIdx.x;   // over NROW*96
    if (idx >= NROW * XDBL_W) return;
    const int n = idx / XDBL_W;
    const int m = idx - n * XDBL_W;
    float s = 0.0f;
#pragma unroll
    for (int sl = 0; sl < XSPLIT; sl++)
        s += g_xpart[((size_t)sl * NROW + n) * 128 + m];
    g_xdbl[idx]    = s;
    g_xdbl_bf[idx] = __float2bfloat16_rn(s);
}

// ---------------------------------------------------------------------------
// LayerNorm: one block per row n; writes h[n][d] bf16.
// ---------------------------------------------------------------------------
__global__ void ln_kernel(const float* __restrict__ x,
                          const float* __restrict__ gamma,
                          const float* __restrict__ beta) {
    const int row = blockIdx.x;
    const int tid = threadIdx.x;           // 256
    const float4 v = *(const float4*)(x + (size_t)row * D_MODEL + tid * 4);

    float s  = v.x + v.y + v.z + v.w;
    float sq = v.x * v.x + v.y * v.y + v.z * v.z + v.w * v.w;

    __shared__ float red_s[8], red_q[8];
    for (int o = 16; o > 0; o >>= 1) {
        s  += __shfl_xor_sync(0xffffffffu, s, o);
        sq += __shfl_xor_sync(0xffffffffu, sq, o);
    }
    const int wid = tid >> 5, lid = tid & 31;
    if (lid == 0) { red_s[wid] = s; red_q[wid] = sq; }
    __syncthreads();
    if (wid == 0) {
        s  = red_s[lid & 7];
        sq = red_q[lid & 7];
        for (int o = 4; o > 0; o >>= 1) {
            s  += __shfl_xor_sync(0xffffffffu, s, o);
            sq += __shfl_xor_sync(0xffffffffu, sq, o);
        }
        if (lid == 0) { red_s[0] = s; red_q[0] = sq; }
    }
    __syncthreads();
    const float mean = red_s[0] * (1.0f / D_MODEL);
    const float var  = red_q[0] * (1.0f / D_MODEL) - mean * mean;
    const float rstd = rsqrtf(var + 1e-6f);

    const int d0 = tid * 4;
    const float4 g4 = *(const float4*)(gamma + d0);
    const float4 b4 = *(const float4*)(beta + d0);
    const float o0 = (v.x - mean) * rstd * g4.x + b4.x;
    const float o1 = (v.y - mean) * rstd * g4.y + b4.y;
    const float o2 = (v.z - mean) * rstd * g4.z + b4.z;
    const float o3 = (v.w - mean) * rstd * g4.w + b4.w;
    __nv_bfloat162 p01 = __floats2bfloat162_rn(o0, o1);
    __nv_bfloat162 p23 = __floats2bfloat162_rn(o2, o3);
    uint2 u = make_uint2(*(uint32_t*)&p01, *(uint32_t*)&p23);
    *(uint2*)(g_h + (size_t)row * D_MODEL + d0) = u;
}

// ---------------------------------------------------------------------------
// Depthwise causal conv(k=4)+bias+SiLU. uct bf16 [n][d]; ucl fp32 [b][d][l].
// ---------------------------------------------------------------------------
__global__ __launch_bounds__(256)
void conv_kernel(const float* __restrict__ conv_w,
                 const float* __restrict__ conv_b) {
    __shared__ float s_in[67][33];
    __shared__ float s_out[64][33];
    const int tid = threadIdx.x;
    const int d0  = blockIdx.x * 32;
    const int l0  = blockIdx.y * 64;
    const int b   = blockIdx.z;

    for (int base = tid; base < 67 * 32; base += 256) {
        const int r = base >> 5;
        const int c = base & 31;
        const int l = l0 - 3 + r;
        float v = 0.0f;
        if (l >= 0) v = g_xzT[((size_t)b * L_SEQ + l) * E2 + d0 + c];
        s_in[r][c] = v;
    }
    __syncthreads();

    for (int base = tid; base < 64 * 32; base += 256) {
        const int ll = base >> 5;
        const int c  = base & 31;
        const int d  = d0 + c;
        const float4 w = *(const float4*)(conv_w + d * 4);
        float s = conv_b[d];
        s = fmaf(w.x, s_in[ll + 0][c], s);
        s = fmaf(w.y, s_in[ll + 1][c], s);
        s = fmaf(w.z, s_in[ll + 2][c], s);
        s = fmaf(w.w, s_in[ll + 3][c], s);
        const float v = s / (1.0f + expf(-s));
        s_out[ll][c] = v;
        g_uct[((size_t)b * L_SEQ + l0 + ll) * D_INNER + d] = __float2bfloat16_rn(v);
    }
    __syncthreads();

    const int ll = tid & 63;
    const int cg = tid >> 6;   // 0..3
#pragma unroll
    for (int j = 0; j < 8; j++) {
        const int c = cg * 8 + j;
        g_ucl[((size_t)b * D_INNER + d0 + c) * L_SEQ + l0 + ll] = s_out[ll][c];
    }
}

// ---------------------------------------------------------------------------
// Selective scan. Half-warp (16 lanes = 16 states) per channel d.
// All inputs fp32. Writes ysc[n][d] fp32 (pre-silu(z)).
// ---------------------------------------------------------------------------
__global__ __launch_bounds__(256)
void scan_kernel(const float* __restrict__ A_log,
                 const float* __restrict__ Dvec) {
    const int tid  = threadIdx.x;
    const int lane = tid & 31;
    const int n    = lane & 15;
    const int half = lane >> 4;
    const int w    = tid >> 5;
    const int d    = blockIdx.x * 16 + w * 2 + half;
    const int b    = blockIdx.y;

    const float An = -expf(A_log[d * D_STATE + n]);
    const float Dd = Dvec[d];

    const float* dp = g_deltaT + (size_t)b * L_SEQ * D_INNER + d;
    const float* up = g_ucl    + ((size_t)b * D_INNER + d) * L_SEQ;
    const float* xd = g_xdbl   + (size_t)b * L_SEQ * XDBL_W;
    float*       yp = g_ysc    + (size_t)b * L_SEQ * D_INNER + d;

    float state = 0.0f;

#pragma unroll 4
    for (int l = 0; l < L_SEQ; l++) {
        const float dv = __ldg(dp + (size_t)l * D_INNER);
        const float u  = __ldg(up + l);
        const float Bn = __ldg(xd + (size_t)l * XDBL_W + DT_RANK + n);
        const float Cn = __ldg(xd + (size_t)l * XDBL_W + DT_RANK + D_STATE + n);

        const float dA = __expf(dv * An);
        state = fmaf(dA, state, dv * Bn * u);

        float yc = state * Cn;
        yc += __shfl_xor_sync(0xffffffffu, yc, 1);
        yc += __shfl_xor_sync(0xffffffffu, yc, 2);
        yc += __shfl_xor_sync(0xffffffffu, yc, 4);
        yc += __shfl_xor_sync(0xffffffffu, yc, 8);

        if (n == 0) {
            yp[(size_t)l * D_INNER] = yc + u * Dd;
        }
    }
}

// ---------------------------------------------------------------------------
// yt = bf16(ysc * silu(z)).  z = xzT[n][2048+d].
// ---------------------------------------------------------------------------
__global__ void ymult_kernel() {
    const size_t i = (size_t)blockIdx.x * 256 + threadIdx.x;
    const int nrow = (int)(i >> 9);
    const int d4   = ((int)i & 511) * 4;
    const float4 z4 = *(const float4*)(g_xzT + (size_t)nrow * E2 + D_INNER + d4);
    const float4 y4 = *(const float4*)(g_ysc + (size_t)nrow * D_INNER + d4);
    const float r0 = y4.x * (z4.x / (1.0f + expf(-z4.x)));
    const float r1 = y4.y * (z4.y / (1.0f + expf(-z4.y)));
    const float r2 = y4.z * (z4.z / (1.0f + expf(-z4.z)));
    const float r3 = y4.w * (z4.w / (1.0f + expf(-z4.w)));
    __nv_bfloat162 p01 = __floats2bfloat162_rn(r0, r1);
    __nv_bfloat162 p23 = __floats2bfloat162_rn(r2, r3);
    uint2 u = make_uint2(*(uint32_t*)&p01, *(uint32_t*)&p23);
    *(uint2*)(g_yt + (size_t)nrow * D_INNER + d4) = u;
}

// ---------------------------------------------------------------------------
// Launch
// ---------------------------------------------------------------------------
extern "C" void kernel_launch(void* const* d_in, const int* in_sizes, int n_in,
                              void* d_out, int out_size) {
    const float* x        = (const float*)d_in[0];
    const float* ln_gamma = (const float*)d_in[1];
    const float* ln_beta  = (const float*)d_in[2];
    const float* in_proj  = (const float*)d_in[3];
    const float* conv_w   = (const float*)d_in[4];
    const float* conv_b   = (const float*)d_in[5];
    const float* x_proj   = (const float*)d_in[6];
    const float* dt_proj  = (const float*)d_in[7];
    const float* dt_pb    = (const float*)d_in[8];
    const float* A_log    = (const float*)d_in[9];
    const float* Dvec     = (const float*)d_in[10];
    const float* out_proj = (const float*)d_in[11];
    float* out = (float*)d_out;

    float *xzT, *deltaT, *xpart, *xdbl;
    __nv_bfloat16 *h, *uct, *yt, *win, *wx, *wdt, *wout, *xdbl_bf;
    cudaGetSymbolAddress((void**)&h,       g_h);
    cudaGetSymbolAddress((void**)&xzT,     g_xzT);
    cudaGetSymbolAddress((void**)&uct,     g_uct);
    cudaGetSymbolAddress((void**)&xdbl,    g_xdbl);
    cudaGetSymbolAddress((void**)&xdbl_bf, g_xdbl_bf);
    cudaGetSymbolAddress((void**)&deltaT,  g_deltaT);
    cudaGetSymbolAddress((void**)&yt,      g_yt);
    cudaGetSymbolAddress((void**)&win,     g_win);
    cudaGetSymbolAddress((void**)&wx,      g_wx);
    cudaGetSymbolAddress((void**)&wdt,     g_wdt);
    cudaGetSymbolAddress((void**)&wout,    g_wout);
    cudaGetSymbolAddress((void**)&xpart,   g_xpart);

    static bool attr_set = false;
    if (!attr_set) {
        cudaFuncSetAttribute(gemm_bf<0>, cudaFuncAttributeMaxDynamicSharedMemorySize, GSMEM_BYTES);
        cudaFuncSetAttribute(gemm_bf<1>, cudaFuncAttributeMaxDynamicSharedMemorySize, GSMEM_BYTES);
        cudaFuncSetAttribute(gemm_bf<2>, cudaFuncAttributeMaxDynamicSharedMemorySize, GSMEM_BYTES);
        cudaFuncSetAttribute(gemm_bf<3>, cudaFuncAttributeMaxDynamicSharedMemorySize, GSMEM_BYTES);
        attr_set = true;
    }

    // 0. convert weights to bf16
    {
        int t;
        t = E2 * D_MODEL / 4;
        cvt_w_kernel<<<(t + 255) / 256, 256>>>(in_proj, win, E2, D_MODEL, t);
        t = 128 * D_INNER / 4;
        cvt_w_kernel<<<(t + 255) / 256, 256>>>(x_proj, wx, XDBL_W, D_INNER, t);
        t = D_INNER * DT_RANK / 4;
        cvt_w_kernel<<<(t + 255) / 256, 256>>>(dt_proj, wdt, D_INNER, DT_RANK, t);
        t = D_MODEL * D_INNER / 4;
        cvt_w_kernel<<<(t + 255) / 256, 256>>>(out_proj, wout, D_MODEL, D_INNER, t);
    }

    // 1. LayerNorm -> h[n][d] bf16
    ln_kernel<<<NROW, 256>>>(x, ln_gamma, ln_beta);

    // 2. in_proj: xzT[n][e] = h[n][:] . Win[e][:]
    gemm_bf<0><<<dim3(NROW / 128, E2 / 128), 128, GSMEM_BYTES>>>(
        win, D_MODEL, D_MODEL, h, D_MODEL, xzT, E2, nullptr);

    // 3. conv + SiLU
    conv_kernel<<<dim3(D_INNER / 32, L_SEQ / 64, B_SZ), 256>>>(conv_w, conv_b);

    // 4. x_proj split-K partials, then reduce -> xdbl (fp32 + bf16)
    gemm_bf<3><<<dim3(NROW / 128, 1, XSPLIT), 128, GSMEM_BYTES>>>(
        wx, D_INNER, D_INNER / XSPLIT, uct, D_INNER, xpart, 128, nullptr);
    reduce_x_kernel<<<(NROW * XDBL_W + 255) / 256, 256>>>();

    // 5. dt_proj (tensor) + bias + softplus -> deltaT[n][d] fp32
    gemm_bf<2><<<dim3(NROW / 128, D_INNER / 128), 128, GSMEM_BYTES>>>(
        wdt, DT_RANK, DT_RANK, xdbl_bf, XDBL_W, deltaT, D_INNER, dt_pb);

    // 6. selective scan -> ysc[n][d] fp32
    scan_kernel<<<dim3(D_INNER / 16, B_SZ), 256>>>(A_log, Dvec);

    // 7. yt = bf16(ysc * silu(z))
    ymult_kernel<<<(NROW * D_INNER / 4) / 256, 256>>>();

    // 8. out_proj + residual: out[n][e] = yt[n][:] . Wout[e][:] + x
    gemm_bf<1><<<dim3(NROW / 128, D_MODEL / 128), 128, GSMEM_BYTES>>>(
        wout, D_INNER, D_INNER, yt, D_INNER, out, D_MODEL, x);
}